// round 13
// baseline (speedup 1.0000x reference)
#include <cuda_runtime.h>
#include <cuda_bf16.h>
#include <math.h>

#define BB 2
#define NN 2048
#define DDIM 128
#define KNBR 128
#define NLAYER 4
#define PP (BB*NN)          // 4096 points
#define HCAT 259            // 3 + 128 + 128

typedef unsigned long long ull;

__device__ __forceinline__ ull pk2(float lo, float hi) {
    ull r; asm("mov.b64 %0, {%1, %2};" : "=l"(r) : "f"(lo), "f"(hi)); return r;
}
__device__ __forceinline__ float2 upk2(ull v) {
    float2 r; asm("mov.b64 {%0, %1}, %2;" : "=f"(r.x), "=f"(r.y) : "l"(v)); return r;
}
__device__ __forceinline__ void ffma2(ull& d, ull a, ull b) {
    asm("fma.rn.f32x2 %0, %1, %2, %0;" : "+l"(d) : "l"(a), "l"(b));
}

// ---------------- scratch (device globals) ----------------
__device__ int            g_idx[PP*KNBR];
__device__ float4         g_rel4[PP*KNBR];
__device__ __nv_bfloat16  g_vh[PP*DDIM];
__device__ float          g_qs[PP];
__device__ float          g_ks[PP];
__device__ float          g_aggv[PP*DDIM];
__device__ float          g_aggh[PP*DDIM];
__device__ float          g_t1[PP*DDIM];
__device__ float          g_fA[PP*DDIM];
__device__ float          g_fB[PP*DDIM];
__device__ float          g_wqcs[NLAYER*DDIM];
__device__ float          g_wkcs[NLAYER*DDIM];
__device__ float          g_w2cs[NLAYER*DDIM];
__device__ float          g_scal[NLAYER*4];
__device__ float4         g_pe4[NLAYER*DDIM];   // w2-scaled, sign-sorted
__device__ int            g_npos[NLAYER];
__device__ float          g_temb[BB*DDIM];
__device__ float          g_h1[PP*DDIM];
__device__ float          g_h2[PP*DDIM];

// ================= KNN =================
__global__ void knn_kernel(const float* __restrict__ xyz) {
    __shared__ float xs[NN*3];
    __shared__ float dsh[NN];
    __shared__ int   red[8];
    __shared__ int   slot;

    int p = blockIdx.x;
    int b = p >> 11;
    int n = p & 2047;
    int tid  = threadIdx.x;
    int lane = tid & 31, wid = tid >> 5;

    const float4* X4 = (const float4*)(xyz + (size_t)b * NN * 3);
    float4* xs4 = (float4*)xs;
    #pragma unroll
    for (int i = tid; i < (NN*3)/4; i += 256) xs4[i] = X4[i];
    __syncthreads();

    float x0 = xs[n*3+0], y0 = xs[n*3+1], z0 = xs[n*3+2];
    float sq0 = x0*x0 + y0*y0 + z0*z0;

    unsigned ul[8];
    #pragma unroll
    for (int i = 0; i < 8; i++) {
        int m = tid + (i << 8);
        float xm = xs[m*3+0], ym = xs[m*3+1], zm = xs[m*3+2];
        float sqm = xm*xm + ym*ym + zm*zm;
        float dot = x0*xm + y0*ym + z0*zm;
        float d = sq0 + sqm - 2.0f*dot;
        dsh[m] = d;
        unsigned u = __float_as_uint(d);
        ul[i] = (u & 0x80000000u) ? ~u : (u | 0x80000000u);
    }
    __syncthreads();

    unsigned lo = 0x80000000u, hi = 0xFFFFFFFFu;
    while (lo < hi) {
        unsigned mid = lo + ((hi - lo) >> 1);
        int c = 0;
        #pragma unroll
        for (int i = 0; i < 8; i++) c += (ul[i] <= mid);
        #pragma unroll
        for (int o = 16; o; o >>= 1) c += __shfl_xor_sync(0xffffffffu, c, o);
        if (!lane) red[wid] = c;
        __syncthreads();
        int tot = red[0]+red[1]+red[2]+red[3]+red[4]+red[5]+red[6]+red[7];
        if (tot >= KNBR) hi = mid; else lo = mid + 1;
        __syncthreads();
    }
    unsigned ustar = lo;

    int c2 = 0;
    #pragma unroll
    for (int i = 0; i < 8; i++) c2 += (ul[i] < ustar);
    #pragma unroll
    for (int o = 16; o; o >>= 1) c2 += __shfl_xor_sync(0xffffffffu, c2, o);
    if (!lane) red[wid] = c2;
    __syncthreads();
    int c_lt = red[0]+red[1]+red[2]+red[3]+red[4]+red[5]+red[6]+red[7];
    int r = KNBR - c_lt;

    if (tid == 0) slot = 0;
    __syncthreads();

    #pragma unroll
    for (int i = 0; i < 8; i++) {
        int m = tid + (i << 8);
        bool sel = false;
        if (ul[i] < ustar) sel = true;
        else if (ul[i] == ustar && r > 0) {
            unsigned mybits = __float_as_uint(dsh[m]);
            int rk = 0;
            for (int mm = 0; mm < m; ++mm)
                rk += (__float_as_uint(dsh[mm]) == mybits);
            if (rk < r) sel = true;
        }
        if (sel) {
            int s = atomicAdd(&slot, 1);
            size_t o = (size_t)p * KNBR + s;
            g_idx[o] = b * NN + m;
            g_rel4[o] = make_float4(x0 - xs[m*3+0], y0 - xs[m*3+1], z0 - xs[m*3+2], 0.f);
        }
    }
}

// ================= prep for ALL layers (grid (NLAYER,4)) =================
__global__ void prep_all(const float* __restrict__ Wq, const float* __restrict__ bq,
                         const float* __restrict__ Wk, const float* __restrict__ bk,
                         const float* __restrict__ Wp2, const float* __restrict__ bp2) {
    int l = blockIdx.x, kind = blockIdx.y, tid = threadIdx.x;
    if (kind < 3) {
        const float* W = (kind == 0 ? Wq : kind == 1 ? Wk : Wp2) + (size_t)l * DDIM * DDIM;
        float* dst = (kind == 0 ? g_wqcs : kind == 1 ? g_wkcs : g_w2cs) + l * DDIM;
        int seg = tid & 3;
        int rbase = tid >> 2;
        for (int rr = 0; rr < DDIM; rr += 32) {
            int rrow = rbase + rr;
            const float4* row = (const float4*)(W + (size_t)rrow * DDIM + seg * 32);
            float s = 0.f;
            #pragma unroll
            for (int j = 0; j < 8; j++) { float4 v = row[j]; s += v.x + v.y + v.z + v.w; }
            s += __shfl_xor_sync(0xffffffffu, s, 1);
            s += __shfl_xor_sync(0xffffffffu, s, 2);
            if (seg == 0) dst[rrow] = s;
        }
    } else {
        int w = tid >> 5, lane = tid & 31;
        if (w < 3) {
            const float* bb = (w == 0 ? bq : w == 1 ? bk : bp2) + l * DDIM;
            float s = bb[lane] + bb[lane+32] + bb[lane+64] + bb[lane+96];
            #pragma unroll
            for (int o = 16; o; o >>= 1) s += __shfl_xor_sync(0xffffffffu, s, o);
            if (!lane) g_scal[l*4 + w] = s;
        }
    }
}

// ================= prep2: scaled + sign-sorted pe weights =================
__global__ void prep2(const float* __restrict__ Wp1, const float* __restrict__ bp1) {
    __shared__ int cntP[4];
    int l = blockIdx.x, tid = threadIdx.x, lane = tid & 31, wid = tid >> 5;
    const float* W = Wp1 + (size_t)l * 3 * DDIM;
    const float* bp = bp1 + l * DDIM;
    float w2 = g_w2cs[l*DDIM + tid];
    bool pos = w2 > 0.f;
    unsigned bal = __ballot_sync(0xffffffffu, pos);
    int wp = __popc(bal & ((1u << lane) - 1u));
    if (!lane) cntP[wid] = __popc(bal);
    __syncthreads();
    int offP = 0, npos = 0;
    #pragma unroll
    for (int w = 0; w < 4; w++) {
        if (w < wid) offP += cntP[w];
        npos += cntP[w];
    }
    int offN = wid * 32 - offP;
    int wn = lane - wp;
    int dest = pos ? (offP + wp) : (npos + offN + wn);
    g_pe4[l*DDIM + dest] = make_float4(W[tid]*w2, W[DDIM+tid]*w2, W[2*DDIM+tid]*w2, bp[tid]*w2);
    if (tid == 0) g_npos[l] = npos;
}

// ================= GEMM v5: 256 threads, BM=16, warp->2 rows x 2 cols =========
// MODE: 0 = +bias fp32; 1 = +bias+Add; 2 = Res+gamma*(acc+bias); 3 = +bias bf16 out + fused qs/ks
// LNA: LayerNorm+ReLU on A rows (K=128); CAT: A assembled from [x_t | fused | temb]
template<int MODE, bool LNA, bool CAT, int KK, int KPP>
__global__ void __launch_bounds__(256) gemm_v5(
    const float* __restrict__ A,
    const float* __restrict__ W,
    const float* __restrict__ bias,
    void* __restrict__ Cv,
    const float* __restrict__ Add,
    const float* __restrict__ Res,
    const float* __restrict__ gammaPtr,
    const float* __restrict__ lng, const float* __restrict__ lnb,
    const float* __restrict__ wq, const float* __restrict__ wk,
    const float* __restrict__ scal2,
    float* __restrict__ qs, float* __restrict__ ks,
    const float* __restrict__ xt, const float* __restrict__ te)
{
    extern __shared__ float sm[];
    float* As = sm;                 // 16 * KPP
    float* Wt = sm + 16 * KPP;      // 64 * KPP

    int tid = threadIdx.x, tx = tid & 31, wrp = tid >> 5;   // 8 warps
    int row0 = blockIdx.x * 16, ny = blockIdx.y;

    // ---- A tile (256 threads)
    if (CAT) {
        #pragma unroll 2
        for (int i = tid; i < 16*KPP; i += 256) {
            int rr = i / KPP, c = i - rr*KPP;
            int row = row0 + rr;
            float v = 0.f;
            if (c < 3)        v = xt[row*3 + c];
            else if (c < 131) v = A[(size_t)row*DDIM + (c-3)];
            else if (c < 259) v = te[(row >> 11)*DDIM + (c-131)];
            As[i] = v;
        }
    } else {
        constexpr int K4 = KK >> 2, KP4 = KPP >> 2;
        const float4* A4 = (const float4*)A;
        float4* As4 = (float4*)As;
        #pragma unroll 2
        for (int i = tid; i < 16*KP4; i += 256) {
            int rr = i / KP4, c = i - rr*KP4;
            As4[i] = (c < K4) ? A4[(size_t)(row0+rr)*K4 + c] : make_float4(0.f,0.f,0.f,0.f);
        }
    }

    // ---- W half, transposed into Wt[c][k] (256 threads)
    {
        #pragma unroll 2
        for (int i = tid; i < 16*KPP; i += 256) {
            int c = i & 63, kb4 = i >> 6;
            int k0 = kb4 << 2;
            float w0 = (k0+0 < KK) ? W[(size_t)(k0+0)*128 + ny*64 + c] : 0.f;
            float w1 = (k0+1 < KK) ? W[(size_t)(k0+1)*128 + ny*64 + c] : 0.f;
            float w2 = (k0+2 < KK) ? W[(size_t)(k0+2)*128 + ny*64 + c] : 0.f;
            float w3 = (k0+3 < KK) ? W[(size_t)(k0+3)*128 + ny*64 + c] : 0.f;
            *(float4*)&Wt[c*KPP + k0] = make_float4(w0, w1, w2, w3);
        }
    }
    __syncthreads();

    // ---- optional LN+ReLU on A rows (K==128): 16 threads per row
    if (LNA) {
        int rrow = tid >> 4, seg = tid & 15;
        float* rowp = As + rrow*KPP + seg*8;
        float s = 0.f;
        #pragma unroll
        for (int j = 0; j < 8; j++) s += rowp[j];
        s += __shfl_xor_sync(0xffffffffu, s, 1);
        s += __shfl_xor_sync(0xffffffffu, s, 2);
        s += __shfl_xor_sync(0xffffffffu, s, 4);
        s += __shfl_xor_sync(0xffffffffu, s, 8);
        float mean = s * 0.0078125f;
        float q = 0.f;
        #pragma unroll
        for (int j = 0; j < 8; j++) { float d = rowp[j] - mean; q = fmaf(d, d, q); }
        q += __shfl_xor_sync(0xffffffffu, q, 1);
        q += __shfl_xor_sync(0xffffffffu, q, 2);
        q += __shfl_xor_sync(0xffffffffu, q, 4);
        q += __shfl_xor_sync(0xffffffffu, q, 8);
        float rstd = rsqrtf(q * 0.0078125f + 1e-5f);
        #pragma unroll
        for (int j = 0; j < 8; j++) {
            int c = seg*8 + j;
            rowp[j] = fmaxf(fmaf((rowp[j]-mean)*rstd, __ldg(&lng[c]), __ldg(&lnb[c])), 0.f);
        }
        __syncthreads();
    }

    // ---- fused qs/ks (v-gemm, half 0): 16 threads per row
    if (MODE == 3 && ny == 0) {
        int rrow = tid >> 4, seg = tid & 15;
        const float* rowp = As + rrow*KPP + seg*8;
        float dq = 0.f, dk = 0.f;
        #pragma unroll
        for (int j = 0; j < 8; j++) {
            float a = rowp[j];
            dq = fmaf(a, __ldg(&wq[seg*8+j]), dq);
            dk = fmaf(a, __ldg(&wk[seg*8+j]), dk);
        }
        dq += __shfl_xor_sync(0xffffffffu, dq, 1);
        dq += __shfl_xor_sync(0xffffffffu, dq, 2);
        dq += __shfl_xor_sync(0xffffffffu, dq, 4);
        dq += __shfl_xor_sync(0xffffffffu, dq, 8);
        dk += __shfl_xor_sync(0xffffffffu, dk, 1);
        dk += __shfl_xor_sync(0xffffffffu, dk, 2);
        dk += __shfl_xor_sync(0xffffffffu, dk, 4);
        dk += __shfl_xor_sync(0xffffffffu, dk, 8);
        if (seg == 0) {
            qs[row0 + rrow] = dq + __ldg(&scal2[0]);
            ks[row0 + rrow] = dk + __ldg(&scal2[1]);
        }
    }

    // ---- main loop: warp -> rows {wrp*2, wrp*2+1}; lane -> cols {tx, tx+32}
    ull acc[2][2];
    acc[0][0] = pk2(0.f,0.f); acc[0][1] = pk2(0.f,0.f);
    acc[1][0] = pk2(0.f,0.f); acc[1][1] = pk2(0.f,0.f);

    const float* a0 = As + (wrp*2+0)*KPP;
    const float* a1 = As + (wrp*2+1)*KPP;
    const float* w0p = Wt + tx*KPP;
    const float* w1p = Wt + (tx+32)*KPP;

    #pragma unroll 4
    for (int kb = 0; kb < KPP; kb += 4) {
        float4 wa = *(const float4*)&w0p[kb];
        float4 wb = *(const float4*)&w1p[kb];
        ull waL = pk2(wa.x, wa.y), waH = pk2(wa.z, wa.w);
        ull wbL = pk2(wb.x, wb.y), wbH = pk2(wb.z, wb.w);
        float4 v0 = *(const float4*)&a0[kb];
        float4 v1 = *(const float4*)&a1[kb];
        ull p0L = pk2(v0.x, v0.y), p0H = pk2(v0.z, v0.w);
        ull p1L = pk2(v1.x, v1.y), p1H = pk2(v1.z, v1.w);
        ffma2(acc[0][0], p0L, waL); ffma2(acc[0][0], p0H, waH);
        ffma2(acc[1][0], p1L, waL); ffma2(acc[1][0], p1H, waH);
        ffma2(acc[0][1], p0L, wbL); ffma2(acc[0][1], p0H, wbH);
        ffma2(acc[1][1], p1L, wbL); ffma2(acc[1][1], p1H, wbH);
    }

    // ---- epilogue
    int c0 = ny*64 + tx, c1 = c0 + 32;
    float b0 = __ldg(&bias[c0]), b1 = __ldg(&bias[c1]);
    float gmv = (MODE == 2) ? __ldg(gammaPtr) : 0.f;

    #pragma unroll
    for (int rr = 0; rr < 2; rr++) {
        int row = row0 + wrp*2 + rr;
        float2 s0 = upk2(acc[rr][0]);
        float2 s1 = upk2(acc[rr][1]);
        float v0 = s0.x + s0.y + b0;
        float v1 = s1.x + s1.y + b1;
        if (MODE == 1) {
            v0 += Add[(size_t)row*128 + c0];
            v1 += Add[(size_t)row*128 + c1];
        }
        if (MODE == 2) {
            v0 = fmaf(gmv, v0, Res[(size_t)row*128 + c0]);
            v1 = fmaf(gmv, v1, Res[(size_t)row*128 + c1]);
        }
        if (MODE == 3) {
            __nv_bfloat16* C = (__nv_bfloat16*)Cv;
            C[(size_t)row*128 + c0] = __float2bfloat16(v0);
            C[(size_t)row*128 + c1] = __float2bfloat16(v1);
        } else {
            float* C = (float*)Cv;
            C[(size_t)row*128 + c0] = v0;
            C[(size_t)row*128 + c1] = v1;
        }
    }
}

// ================= attention v5 (best-known) =================
__global__ void __launch_bounds__(128) attn5(
    const float4* __restrict__ pe4, const int* __restrict__ nposPtr,
    const float* __restrict__ Wp1, const float* __restrict__ bp1,
    const float* __restrict__ scal)
{
    __shared__ float4 sp4[DDIM];
    __shared__ float4 relq[KNBR];
    __shared__ int    ids[KNBR];
    __shared__ float  pl[4*KNBR];
    __shared__ float  red[8];
    __shared__ float  rv[4*DDIM];
    __shared__ float  rh[4*DDIM];

    int p = blockIdx.x, tid = threadIdx.x, lane = tid & 31, wrp = tid >> 5;

    sp4[tid] = __ldg(&pe4[tid]);

    size_t base = (size_t)p * KNBR + tid;
    float4 rq = g_rel4[base];
    int gm = g_idx[base];
    relq[tid] = rq;
    ids[tid] = gm;
    int npos = __ldg(nposPtr);
    __syncthreads();

    {
        float4 r0 = relq[lane];
        float4 r1 = relq[lane + 32];
        float4 r2 = relq[lane + 64];
        float4 r3 = relq[lane + 96];
        float d0 = 0.f, d1 = 0.f, d2 = 0.f, d3 = 0.f;
        int dbase = wrp * 32;
        #pragma unroll 8
        for (int j = 0; j < 32; j++) {
            int d = dbase + j;
            float4 w = sp4[d];
            float h0 = fmaf(r0.x, w.x, fmaf(r0.y, w.y, fmaf(r0.z, w.z, w.w)));
            float h1 = fmaf(r1.x, w.x, fmaf(r1.y, w.y, fmaf(r1.z, w.z, w.w)));
            float h2 = fmaf(r2.x, w.x, fmaf(r2.y, w.y, fmaf(r2.z, w.z, w.w)));
            float h3 = fmaf(r3.x, w.x, fmaf(r3.y, w.y, fmaf(r3.z, w.z, w.w)));
            if (d < npos) {
                d0 += fmaxf(h0, 0.f); d1 += fmaxf(h1, 0.f);
                d2 += fmaxf(h2, 0.f); d3 += fmaxf(h3, 0.f);
            } else {
                d0 += fminf(h0, 0.f); d1 += fminf(h1, 0.f);
                d2 += fminf(h2, 0.f); d3 += fminf(h3, 0.f);
            }
        }
        pl[wrp*KNBR + lane]      = d0;
        pl[wrp*KNBR + lane + 32] = d1;
        pl[wrp*KNBR + lane + 64] = d2;
        pl[wrp*KNBR + lane + 96] = d3;
    }
    __syncthreads();

    float dot = pl[tid] + pl[KNBR+tid] + pl[2*KNBR+tid] + pl[3*KNBR+tid];
    float logit = g_qs[p] - g_ks[gm] + dot + __ldg(&scal[2]);

    float mx = logit;
    #pragma unroll
    for (int o = 16; o; o >>= 1) mx = fmaxf(mx, __shfl_xor_sync(0xffffffffu, mx, o));
    if (!lane) red[wrp] = mx;
    __syncthreads();
    mx = fmaxf(fmaxf(red[0], red[1]), fmaxf(red[2], red[3]));
    float e = expf(logit - mx);
    float ss = e;
    #pragma unroll
    for (int o = 16; o; o >>= 1) ss += __shfl_xor_sync(0xffffffffu, ss, o);
    if (!lane) red[4 + wrp] = ss;
    __syncthreads();
    ss = red[4] + red[5] + red[6] + red[7];
    rq.w = e / ss;
    relq[tid] = rq;
    __syncthreads();

    float4 WX = __ldg((const float4*)&Wp1[lane*4]);
    float4 WY = __ldg((const float4*)&Wp1[DDIM + lane*4]);
    float4 WZ = __ldg((const float4*)&Wp1[2*DDIM + lane*4]);
    float4 BV = __ldg((const float4*)&bp1[lane*4]);

    float av0=0.f, av1=0.f, av2=0.f, av3=0.f;
    float ah0=0.f, ah1=0.f, ah2=0.f, ah3=0.f;
    int kbase = wrp * 32;
    const __nv_bfloat16* vbase = g_vh + lane*4;
    #pragma unroll 8
    for (int j = 0; j < 32; j++) {
        float4 rk = relq[kbase + j];
        int id = ids[kbase + j];
        uint2 raw = __ldg((const uint2*)(vbase + (size_t)id * DDIM));
        float2 f01 = __bfloat1622float2(*(__nv_bfloat162*)&raw.x);
        float2 f23 = __bfloat1622float2(*(__nv_bfloat162*)&raw.y);
        float a = rk.w;
        float h0 = fmaxf(fmaf(rk.x,WX.x,fmaf(rk.y,WY.x,fmaf(rk.z,WZ.x,BV.x))), 0.f);
        float h1 = fmaxf(fmaf(rk.x,WX.y,fmaf(rk.y,WY.y,fmaf(rk.z,WZ.y,BV.y))), 0.f);
        float h2 = fmaxf(fmaf(rk.x,WX.z,fmaf(rk.y,WY.z,fmaf(rk.z,WZ.z,BV.z))), 0.f);
        float h3 = fmaxf(fmaf(rk.x,WX.w,fmaf(rk.y,WY.w,fmaf(rk.z,WZ.w,BV.w))), 0.f);
        ah0 = fmaf(a, h0, ah0); ah1 = fmaf(a, h1, ah1);
        ah2 = fmaf(a, h2, ah2); ah3 = fmaf(a, h3, ah3);
        av0 = fmaf(a, f01.x, av0); av1 = fmaf(a, f01.y, av1);
        av2 = fmaf(a, f23.x, av2); av3 = fmaf(a, f23.y, av3);
    }
    *(float4*)&rv[wrp*DDIM + lane*4] = make_float4(av0, av1, av2, av3);
    *(float4*)&rh[wrp*DDIM + lane*4] = make_float4(ah0, ah1, ah2, ah3);
    __syncthreads();

    float sv = rv[tid] + rv[DDIM+tid] + rv[2*DDIM+tid] + rv[3*DDIM+tid];
    float sh = rh[tid] + rh[DDIM+tid] + rh[2*DDIM+tid] + rh[3*DDIM+tid];
    g_aggv[(size_t)p*DDIM + tid] = sv;
    g_aggh[(size_t)p*DDIM + tid] = sh;
}

// ================= timestep embedding MLP v2 =================
__global__ void __launch_bounds__(512) temb_kernel(
    const int* __restrict__ t,
    const float* __restrict__ tW1, const float* __restrict__ tb1,
    const float* __restrict__ tW2, const float* __restrict__ tb2) {
    __shared__ float emb[128], h1[128], part[4*128];
    int b = blockIdx.x;
    int tid = threadIdx.x;
    int d = tid & 127, iq = tid >> 7;

    if (tid < 128) {
        float tv = (float)__ldg(&t[b]);
        if (tid < 64) {
            float f = expf(-logf(10000.f) * (float)tid / 63.f);
            float arg = tv * f;
            emb[tid] = sinf(arg);
            emb[tid + 64] = cosf(arg);
        }
    }
    __syncthreads();

    {
        float a0 = 0.f, a1 = 0.f, a2 = 0.f, a3 = 0.f;
        int i0 = iq * 32;
        #pragma unroll
        for (int j = 0; j < 32; j += 4) {
            a0 = fmaf(emb[i0+j+0], __ldg(&tW1[(i0+j+0)*128 + d]), a0);
            a1 = fmaf(emb[i0+j+1], __ldg(&tW1[(i0+j+1)*128 + d]), a1);
            a2 = fmaf(emb[i0+j+2], __ldg(&tW1[(i0+j+2)*128 + d]), a2);
            a3 = fmaf(emb[i0+j+3], __ldg(&tW1[(i0+j+3)*128 + d]), a3);
        }
        part[iq*128 + d] = (a0 + a1) + (a2 + a3);
    }
    __syncthreads();
    if (tid < 128)
        h1[tid] = fmaxf(part[tid] + part[128+tid] + part[256+tid] + part[384+tid] + __ldg(&tb1[tid]), 0.f);
    __syncthreads();

    {
        float a0 = 0.f, a1 = 0.f, a2 = 0.f, a3 = 0.f;
        int i0 = iq * 32;
        #pragma unroll
        for (int j = 0; j < 32; j += 4) {
            a0 = fmaf(h1[i0+j+0], __ldg(&tW2[(i0+j+0)*128 + d]), a0);
            a1 = fmaf(h1[i0+j+1], __ldg(&tW2[(i0+j+1)*128 + d]), a1);
            a2 = fmaf(h1[i0+j+2], __ldg(&tW2[(i0+j+2)*128 + d]), a2);
            a3 = fmaf(h1[i0+j+3], __ldg(&tW2[(i0+j+3)*128 + d]), a3);
        }
        part[iq*128 + d] = (a0 + a1) + (a2 + a3);
    }
    __syncthreads();
    if (tid < 128)
        g_temb[b*128 + tid] = part[tid] + part[128+tid] + part[256+tid] + part[384+tid] + __ldg(&tb2[tid]);
}

// ================= final LN+ReLU+proj =================
__global__ void out_kernel(const float* __restrict__ g2, const float* __restrict__ be2,
                           const float* __restrict__ W3, const float* __restrict__ b3,
                           float* __restrict__ out) {
    int p = blockIdx.x * 8 + (threadIdx.x >> 5);
    int lane = threadIdx.x & 31;
    float4 f = ((const float4*)(g_h2 + (size_t)p * DDIM))[lane];
    float s = f.x + f.y + f.z + f.w;
    #pragma unroll
    for (int o = 16; o; o >>= 1) s += __shfl_xor_sync(0xffffffffu, s, o);
    float mean = s * 0.0078125f;
    float d0 = f.x-mean, d1 = f.y-mean, d2 = f.z-mean, d3 = f.w-mean;
    float q = d0*d0 + d1*d1 + d2*d2 + d3*d3;
    #pragma unroll
    for (int o = 16; o; o >>= 1) q += __shfl_xor_sync(0xffffffffu, q, o);
    float rstd = rsqrtf(q * 0.0078125f + 1e-5f);
    int i0 = lane * 4;
    float4 gg = *(const float4*)&g2[i0];
    float4 bb = *(const float4*)&be2[i0];
    float v0 = fmaxf(fmaf(d0*rstd, gg.x, bb.x), 0.f);
    float v1 = fmaxf(fmaf(d1*rstd, gg.y, bb.y), 0.f);
    float v2 = fmaxf(fmaf(d2*rstd, gg.z, bb.z), 0.f);
    float v3 = fmaxf(fmaf(d3*rstd, gg.w, bb.w), 0.f);
    float a0 = v0*W3[i0*3+0] + v1*W3[(i0+1)*3+0] + v2*W3[(i0+2)*3+0] + v3*W3[(i0+3)*3+0];
    float a1 = v0*W3[i0*3+1] + v1*W3[(i0+1)*3+1] + v2*W3[(i0+2)*3+1] + v3*W3[(i0+3)*3+1];
    float a2 = v0*W3[i0*3+2] + v1*W3[(i0+1)*3+2] + v2*W3[(i0+2)*3+2] + v3*W3[(i0+3)*3+2];
    #pragma unroll
    for (int o = 16; o; o >>= 1) {
        a0 += __shfl_xor_sync(0xffffffffu, a0, o);
        a1 += __shfl_xor_sync(0xffffffffu, a1, o);
        a2 += __shfl_xor_sync(0xffffffffu, a2, o);
    }
    if (!lane) {
        out[p*3+0] = a0 + b3[0];
        out[p*3+1] = a1 + b3[1];
        out[p*3+2] = a2 + b3[2];
    }
}

#define KPP128 132
#define KPP259 260
#define GS(KPp) (80 * (KPp) * 4)

extern "C" void kernel_launch(void* const* d_in, const int* in_sizes, int n_in,
                              void* d_out, int out_size) {
    const float* xyz   = (const float*)d_in[0];
    const float* feat  = (const float*)d_in[1];
    const float* x_t   = (const float*)d_in[2];
    const int*   t     = (const int*)  d_in[3];
    const float* Wq    = (const float*)d_in[4];
    const float* bq    = (const float*)d_in[5];
    const float* Wk    = (const float*)d_in[6];
    const float* bk    = (const float*)d_in[7];
    const float* Wv    = (const float*)d_in[8];
    const float* bv    = (const float*)d_in[9];
    const float* Wp1   = (const float*)d_in[10];
    const float* bp1   = (const float*)d_in[11];
    const float* Wp2   = (const float*)d_in[12];
    const float* bp2   = (const float*)d_in[13];
    const float* gamma = (const float*)d_in[14];
    const float* Wproj = (const float*)d_in[15];
    const float* bproj = (const float*)d_in[16];
    const float* tW1   = (const float*)d_in[17];
    const float* tb1   = (const float*)d_in[18];
    const float* tW2   = (const float*)d_in[19];
    const float* tb2   = (const float*)d_in[20];
    const float* nW1   = (const float*)d_in[21];
    const float* nb1   = (const float*)d_in[22];
    const float* ng1   = (const float*)d_in[23];
    const float* nbe1  = (const float*)d_in[24];
    const float* nW2   = (const float*)d_in[25];
    const float* nb2   = (const float*)d_in[26];
    const float* ng2   = (const float*)d_in[27];
    const float* nbe2  = (const float*)d_in[28];
    const float* nW3   = (const float*)d_in[29];
    const float* nb3   = (const float*)d_in[30];

    cudaFuncSetAttribute(gemm_v5<3,false,false,128,KPP128>, cudaFuncAttributeMaxDynamicSharedMemorySize, GS(KPP128));
    cudaFuncSetAttribute(gemm_v5<1,false,false,128,KPP128>, cudaFuncAttributeMaxDynamicSharedMemorySize, GS(KPP128));
    cudaFuncSetAttribute(gemm_v5<2,false,false,128,KPP128>, cudaFuncAttributeMaxDynamicSharedMemorySize, GS(KPP128));
    cudaFuncSetAttribute(gemm_v5<0,false,true,HCAT,KPP259>, cudaFuncAttributeMaxDynamicSharedMemorySize, GS(KPP259));
    cudaFuncSetAttribute(gemm_v5<0,true,false,128,KPP128>,  cudaFuncAttributeMaxDynamicSharedMemorySize, GS(KPP128));

    float *paggv, *paggh, *pt1, *pfA, *pfB, *ph1, *ph2, *pqs, *pks;
    float *pwq, *pwk, *psc, *ptemb;
    float4 *ppe4; int *pnpos;
    __nv_bfloat16 *pvh;
    cudaGetSymbolAddress((void**)&pvh,   g_vh);
    cudaGetSymbolAddress((void**)&paggv, g_aggv);
    cudaGetSymbolAddress((void**)&paggh, g_aggh);
    cudaGetSymbolAddress((void**)&pt1,   g_t1);
    cudaGetSymbolAddress((void**)&pfA,   g_fA);
    cudaGetSymbolAddress((void**)&pfB,   g_fB);
    cudaGetSymbolAddress((void**)&ph1,   g_h1);
    cudaGetSymbolAddress((void**)&ph2,   g_h2);
    cudaGetSymbolAddress((void**)&pqs,   g_qs);
    cudaGetSymbolAddress((void**)&pks,   g_ks);
    cudaGetSymbolAddress((void**)&pwq,   g_wqcs);
    cudaGetSymbolAddress((void**)&pwk,   g_wkcs);
    cudaGetSymbolAddress((void**)&psc,   g_scal);
    cudaGetSymbolAddress((void**)&ppe4,  g_pe4);
    cudaGetSymbolAddress((void**)&pnpos, g_npos);
    cudaGetSymbolAddress((void**)&ptemb, g_temb);

    dim3 ggrid(PP/16, 2);
    const float* cur = feat;
    float* bufs[2] = { pfA, pfB };

    // launch order: knn(0), prep_all(1), prep2(2), vgemm l0(3) <- ncu capture
    knn_kernel<<<PP, 256>>>(xyz);
    prep_all<<<dim3(NLAYER,4), 128>>>(Wq, bq, Wk, bk, Wp2, bp2);
    prep2<<<NLAYER, 128>>>(Wp1, bp1);

    for (int l = 0; l < NLAYER; l++) {
        gemm_v5<3,false,false,128,KPP128><<<ggrid, 256, GS(KPP128)>>>(cur,
            Wv + (size_t)l*DDIM*DDIM, bv + l*DDIM, pvh,
            nullptr, nullptr, nullptr, nullptr, nullptr,
            pwq + l*DDIM, pwk + l*DDIM, psc + l*4, pqs, pks,
            nullptr, nullptr);
        if (l == 0)
            temb_kernel<<<BB, 512>>>(t, tW1, tb1, tW2, tb2);
        attn5<<<PP, 128>>>(ppe4 + l*DDIM, pnpos + l,
                           Wp1 + (size_t)l*3*DDIM, bp1 + l*DDIM, psc + l*4);
        gemm_v5<1,false,false,128,KPP128><<<ggrid, 256, GS(KPP128)>>>(paggh,
            Wp2 + (size_t)l*DDIM*DDIM, bp2 + l*DDIM, pt1,
            paggv, nullptr, nullptr, nullptr, nullptr,
            nullptr, nullptr, nullptr, nullptr, nullptr,
            nullptr, nullptr);
        float* nxt = bufs[l & 1];
        gemm_v5<2,false,false,128,KPP128><<<ggrid, 256, GS(KPP128)>>>(pt1,
            Wproj + (size_t)l*DDIM*DDIM, bproj + l*DDIM, nxt,
            nullptr, cur, gamma + l, nullptr, nullptr,
            nullptr, nullptr, nullptr, nullptr, nullptr,
            nullptr, nullptr);
        cur = nxt;
    }

    gemm_v5<0,false,true,HCAT,KPP259><<<ggrid, 256, GS(KPP259)>>>(cur,
        nW1, nb1, ph1,
        nullptr, nullptr, nullptr, nullptr, nullptr,
        nullptr, nullptr, nullptr, nullptr, nullptr,
        x_t, ptemb);
    gemm_v5<0,true,false,128,KPP128><<<ggrid, 256, GS(KPP128)>>>(ph1,
        nW2, nb2, ph2,
        nullptr, nullptr, nullptr, ng1, nbe1,
        nullptr, nullptr, nullptr, nullptr, nullptr,
        nullptr, nullptr);
    out_kernel<<<PP/8, 256>>>(ng2, nbe2, nW3, nb3, (float*)d_out);
}

// round 14
// speedup vs baseline: 1.0425x; 1.0425x over previous
#include <cuda_runtime.h>
#include <cuda_bf16.h>
#include <math.h>

#define BB 2
#define NN 2048
#define DDIM 128
#define KNBR 128
#define NLAYER 4
#define PP (BB*NN)          // 4096 points
#define HCAT 259            // 3 + 128 + 128

typedef unsigned long long ull;

__device__ __forceinline__ ull pk2(float lo, float hi) {
    ull r; asm("mov.b64 %0, {%1, %2};" : "=l"(r) : "f"(lo), "f"(hi)); return r;
}
__device__ __forceinline__ float2 upk2(ull v) {
    float2 r; asm("mov.b64 {%0, %1}, %2;" : "=f"(r.x), "=f"(r.y) : "l"(v)); return r;
}
__device__ __forceinline__ void ffma2(ull& d, ull a, ull b) {
    asm("fma.rn.f32x2 %0, %1, %2, %0;" : "+l"(d) : "l"(a), "l"(b));
}

// ---------------- scratch (device globals) ----------------
__device__ int            g_idx[PP*KNBR];
__device__ float4         g_rel4[PP*KNBR];
__device__ __nv_bfloat16  g_vh[PP*DDIM];
__device__ float          g_qs[PP];
__device__ float          g_ks[PP];
__device__ float          g_aggv[PP*DDIM];
__device__ float          g_aggh[PP*DDIM];
__device__ float          g_t1[PP*DDIM];
__device__ float          g_fA[PP*DDIM];
__device__ float          g_fB[PP*DDIM];
__device__ float          g_wqcs[NLAYER*DDIM];
__device__ float          g_wkcs[NLAYER*DDIM];
__device__ float          g_w2cs[NLAYER*DDIM];
__device__ float          g_scal[NLAYER*4];
__device__ float4         g_pe4[NLAYER*DDIM];   // w2-scaled, sign-sorted
__device__ int            g_npos[NLAYER];
__device__ float          g_temb[BB*DDIM];
__device__ float          g_h1[PP*DDIM];
__device__ float          g_h2[PP*DDIM];

// ================= KNN =================
__global__ void knn_kernel(const float* __restrict__ xyz) {
    __shared__ float xs[NN*3];
    __shared__ float dsh[NN];
    __shared__ int   red[8];
    __shared__ int   slot;

    int p = blockIdx.x;
    int b = p >> 11;
    int n = p & 2047;
    int tid  = threadIdx.x;
    int lane = tid & 31, wid = tid >> 5;

    const float4* X4 = (const float4*)(xyz + (size_t)b * NN * 3);
    float4* xs4 = (float4*)xs;
    #pragma unroll
    for (int i = tid; i < (NN*3)/4; i += 256) xs4[i] = X4[i];
    __syncthreads();

    float x0 = xs[n*3+0], y0 = xs[n*3+1], z0 = xs[n*3+2];
    float sq0 = x0*x0 + y0*y0 + z0*z0;

    unsigned ul[8];
    #pragma unroll
    for (int i = 0; i < 8; i++) {
        int m = tid + (i << 8);
        float xm = xs[m*3+0], ym = xs[m*3+1], zm = xs[m*3+2];
        float sqm = xm*xm + ym*ym + zm*zm;
        float dot = x0*xm + y0*ym + z0*zm;
        float d = sq0 + sqm - 2.0f*dot;
        dsh[m] = d;
        unsigned u = __float_as_uint(d);
        ul[i] = (u & 0x80000000u) ? ~u : (u | 0x80000000u);
    }
    __syncthreads();

    unsigned lo = 0x80000000u, hi = 0xFFFFFFFFu;
    while (lo < hi) {
        unsigned mid = lo + ((hi - lo) >> 1);
        int c = 0;
        #pragma unroll
        for (int i = 0; i < 8; i++) c += (ul[i] <= mid);
        #pragma unroll
        for (int o = 16; o; o >>= 1) c += __shfl_xor_sync(0xffffffffu, c, o);
        if (!lane) red[wid] = c;
        __syncthreads();
        int tot = red[0]+red[1]+red[2]+red[3]+red[4]+red[5]+red[6]+red[7];
        if (tot >= KNBR) hi = mid; else lo = mid + 1;
        __syncthreads();
    }
    unsigned ustar = lo;

    int c2 = 0;
    #pragma unroll
    for (int i = 0; i < 8; i++) c2 += (ul[i] < ustar);
    #pragma unroll
    for (int o = 16; o; o >>= 1) c2 += __shfl_xor_sync(0xffffffffu, c2, o);
    if (!lane) red[wid] = c2;
    __syncthreads();
    int c_lt = red[0]+red[1]+red[2]+red[3]+red[4]+red[5]+red[6]+red[7];
    int r = KNBR - c_lt;

    if (tid == 0) slot = 0;
    __syncthreads();

    #pragma unroll
    for (int i = 0; i < 8; i++) {
        int m = tid + (i << 8);
        bool sel = false;
        if (ul[i] < ustar) sel = true;
        else if (ul[i] == ustar && r > 0) {
            unsigned mybits = __float_as_uint(dsh[m]);
            int rk = 0;
            for (int mm = 0; mm < m; ++mm)
                rk += (__float_as_uint(dsh[mm]) == mybits);
            if (rk < r) sel = true;
        }
        if (sel) {
            int s = atomicAdd(&slot, 1);
            size_t o = (size_t)p * KNBR + s;
            g_idx[o] = b * NN + m;
            g_rel4[o] = make_float4(x0 - xs[m*3+0], y0 - xs[m*3+1], z0 - xs[m*3+2], 0.f);
        }
    }
}

// ================= prep for ALL layers (grid (NLAYER,4)) =================
__global__ void prep_all(const float* __restrict__ Wq, const float* __restrict__ bq,
                         const float* __restrict__ Wk, const float* __restrict__ bk,
                         const float* __restrict__ Wp2, const float* __restrict__ bp2) {
    int l = blockIdx.x, kind = blockIdx.y, tid = threadIdx.x;
    if (kind < 3) {
        const float* W = (kind == 0 ? Wq : kind == 1 ? Wk : Wp2) + (size_t)l * DDIM * DDIM;
        float* dst = (kind == 0 ? g_wqcs : kind == 1 ? g_wkcs : g_w2cs) + l * DDIM;
        int seg = tid & 3;
        int rbase = tid >> 2;
        for (int rr = 0; rr < DDIM; rr += 32) {
            int rrow = rbase + rr;
            const float4* row = (const float4*)(W + (size_t)rrow * DDIM + seg * 32);
            float s = 0.f;
            #pragma unroll
            for (int j = 0; j < 8; j++) { float4 v = row[j]; s += v.x + v.y + v.z + v.w; }
            s += __shfl_xor_sync(0xffffffffu, s, 1);
            s += __shfl_xor_sync(0xffffffffu, s, 2);
            if (seg == 0) dst[rrow] = s;
        }
    } else {
        int w = tid >> 5, lane = tid & 31;
        if (w < 3) {
            const float* bb = (w == 0 ? bq : w == 1 ? bk : bp2) + l * DDIM;
            float s = bb[lane] + bb[lane+32] + bb[lane+64] + bb[lane+96];
            #pragma unroll
            for (int o = 16; o; o >>= 1) s += __shfl_xor_sync(0xffffffffu, s, o);
            if (!lane) g_scal[l*4 + w] = s;
        }
    }
}

// ================= prep2: scaled + sign-sorted pe weights =================
__global__ void prep2(const float* __restrict__ Wp1, const float* __restrict__ bp1) {
    __shared__ int cntP[4];
    int l = blockIdx.x, tid = threadIdx.x, lane = tid & 31, wid = tid >> 5;
    const float* W = Wp1 + (size_t)l * 3 * DDIM;
    const float* bp = bp1 + l * DDIM;
    float w2 = g_w2cs[l*DDIM + tid];
    bool pos = w2 > 0.f;
    unsigned bal = __ballot_sync(0xffffffffu, pos);
    int wp = __popc(bal & ((1u << lane) - 1u));
    if (!lane) cntP[wid] = __popc(bal);
    __syncthreads();
    int offP = 0, npos = 0;
    #pragma unroll
    for (int w = 0; w < 4; w++) {
        if (w < wid) offP += cntP[w];
        npos += cntP[w];
    }
    int offN = wid * 32 - offP;
    int wn = lane - wp;
    int dest = pos ? (offP + wp) : (npos + offN + wn);
    g_pe4[l*DDIM + dest] = make_float4(W[tid]*w2, W[DDIM+tid]*w2, W[2*DDIM+tid]*w2, bp[tid]*w2);
    if (tid == 0) g_npos[l] = npos;
}

// ================= GEMM v6: split-K across warps, 256 threads, BM=16 ==========
// warp wrp -> k-slice s = wrp>>1 ([s*SLICE, s*SLICE+SLICE)), row-group rg = wrp&1
// (rows rg*8..rg*8+8). lane -> cols {tx, tx+32}. Partial C reduced via smem.
// MODE: 0 = +bias fp32; 1 = +bias+Add; 2 = Res+gamma*(acc+bias); 3 = +bias bf16 + qs/ks
// LNA: LayerNorm+ReLU on A rows (K=128); CAT: A from [x_t | fused | temb]
#define PSL_STRIDE 1088      // per-slice floats: 16 rows * 68
template<int MODE, bool LNA, bool CAT, int KK, int KPP, int SLICE>
__global__ void __launch_bounds__(256) gemm_v6(
    const float* __restrict__ A,
    const float* __restrict__ W,
    const float* __restrict__ bias,
    void* __restrict__ Cv,
    const float* __restrict__ Add,
    const float* __restrict__ Res,
    const float* __restrict__ gammaPtr,
    const float* __restrict__ lng, const float* __restrict__ lnb,
    const float* __restrict__ wq, const float* __restrict__ wk,
    const float* __restrict__ scal2,
    float* __restrict__ qs, float* __restrict__ ks,
    const float* __restrict__ xt, const float* __restrict__ te)
{
    extern __shared__ float sm[];
    float* As = sm;                 // 16 * KPP
    float* Wt = sm + 16 * KPP;      // 64 * KPP   (also reused for partials)

    int tid = threadIdx.x, tx = tid & 31, wrp = tid >> 5;
    int row0 = blockIdx.x * 16, ny = blockIdx.y;

    // ---- A tile
    if (CAT) {
        #pragma unroll 2
        for (int i = tid; i < 16*KPP; i += 256) {
            int rr = i / KPP, c = i - rr*KPP;
            int row = row0 + rr;
            float v = 0.f;
            if (c < 3)        v = xt[row*3 + c];
            else if (c < 131) v = A[(size_t)row*DDIM + (c-3)];
            else if (c < 259) v = te[(row >> 11)*DDIM + (c-131)];
            As[i] = v;
        }
    } else {
        constexpr int K4 = KK >> 2, KP4 = KPP >> 2;
        const float4* A4 = (const float4*)A;
        float4* As4 = (float4*)As;
        #pragma unroll 2
        for (int i = tid; i < 16*KP4; i += 256) {
            int rr = i / KP4, c = i - rr*KP4;
            As4[i] = (c < K4) ? A4[(size_t)(row0+rr)*K4 + c] : make_float4(0.f,0.f,0.f,0.f);
        }
    }

    // ---- W half, transposed into Wt[c][k]
    {
        #pragma unroll 2
        for (int i = tid; i < 16*KPP; i += 256) {
            int c = i & 63, kb4 = i >> 6;
            int k0 = kb4 << 2;
            float w0 = (k0+0 < KK) ? W[(size_t)(k0+0)*128 + ny*64 + c] : 0.f;
            float w1 = (k0+1 < KK) ? W[(size_t)(k0+1)*128 + ny*64 + c] : 0.f;
            float w2 = (k0+2 < KK) ? W[(size_t)(k0+2)*128 + ny*64 + c] : 0.f;
            float w3 = (k0+3 < KK) ? W[(size_t)(k0+3)*128 + ny*64 + c] : 0.f;
            *(float4*)&Wt[c*KPP + k0] = make_float4(w0, w1, w2, w3);
        }
    }
    __syncthreads();

    // ---- optional LN+ReLU on A rows (K==128): 16 threads per row
    if (LNA) {
        int rrow = tid >> 4, seg = tid & 15;
        float* rowp = As + rrow*KPP + seg*8;
        float s = 0.f;
        #pragma unroll
        for (int j = 0; j < 8; j++) s += rowp[j];
        s += __shfl_xor_sync(0xffffffffu, s, 1);
        s += __shfl_xor_sync(0xffffffffu, s, 2);
        s += __shfl_xor_sync(0xffffffffu, s, 4);
        s += __shfl_xor_sync(0xffffffffu, s, 8);
        float mean = s * 0.0078125f;
        float q = 0.f;
        #pragma unroll
        for (int j = 0; j < 8; j++) { float d = rowp[j] - mean; q = fmaf(d, d, q); }
        q += __shfl_xor_sync(0xffffffffu, q, 1);
        q += __shfl_xor_sync(0xffffffffu, q, 2);
        q += __shfl_xor_sync(0xffffffffu, q, 4);
        q += __shfl_xor_sync(0xffffffffu, q, 8);
        float rstd = rsqrtf(q * 0.0078125f + 1e-5f);
        #pragma unroll
        for (int j = 0; j < 8; j++) {
            int c = seg*8 + j;
            rowp[j] = fmaxf(fmaf((rowp[j]-mean)*rstd, __ldg(&lng[c]), __ldg(&lnb[c])), 0.f);
        }
        __syncthreads();
    }

    // ---- fused qs/ks (v-gemm, half 0): 16 threads per row
    if (MODE == 3 && ny == 0) {
        int rrow = tid >> 4, seg = tid & 15;
        const float* rowp = As + rrow*KPP + seg*8;
        float dq = 0.f, dk = 0.f;
        #pragma unroll
        for (int j = 0; j < 8; j++) {
            float a = rowp[j];
            dq = fmaf(a, __ldg(&wq[seg*8+j]), dq);
            dk = fmaf(a, __ldg(&wk[seg*8+j]), dk);
        }
        dq += __shfl_xor_sync(0xffffffffu, dq, 1);
        dq += __shfl_xor_sync(0xffffffffu, dq, 2);
        dq += __shfl_xor_sync(0xffffffffu, dq, 4);
        dq += __shfl_xor_sync(0xffffffffu, dq, 8);
        dk += __shfl_xor_sync(0xffffffffu, dk, 1);
        dk += __shfl_xor_sync(0xffffffffu, dk, 2);
        dk += __shfl_xor_sync(0xffffffffu, dk, 4);
        dk += __shfl_xor_sync(0xffffffffu, dk, 8);
        if (seg == 0) {
            qs[row0 + rrow] = dq + __ldg(&scal2[0]);
            ks[row0 + rrow] = dk + __ldg(&scal2[1]);
        }
    }

    // ---- main loop: slice s = wrp>>1, rows rbase = (wrp&1)*8
    int sl = wrp >> 1, rbase = (wrp & 1) * 8;
    ull acc[8][2];
    #pragma unroll
    for (int rr = 0; rr < 8; rr++) { acc[rr][0] = pk2(0.f,0.f); acc[rr][1] = pk2(0.f,0.f); }

    {
        const float* w0p = Wt + tx*KPP;
        const float* w1p = Wt + (tx+32)*KPP;
        const float* ab  = As + rbase*KPP;
        int kend = sl*SLICE + SLICE;
        #pragma unroll 4
        for (int kb = sl*SLICE; kb < kend; kb += 4) {
            float4 wa = *(const float4*)&w0p[kb];
            float4 wb = *(const float4*)&w1p[kb];
            ull waL = pk2(wa.x, wa.y), waH = pk2(wa.z, wa.w);
            ull wbL = pk2(wb.x, wb.y), wbH = pk2(wb.z, wb.w);
            #pragma unroll
            for (int rr = 0; rr < 8; rr++) {
                float4 av = *(const float4*)&ab[rr*KPP + kb];
                ull aL = pk2(av.x, av.y), aH = pk2(av.z, av.w);
                ffma2(acc[rr][0], aL, waL); ffma2(acc[rr][0], aH, waH);
                ffma2(acc[rr][1], aL, wbL); ffma2(acc[rr][1], aH, wbH);
            }
        }
    }
    __syncthreads();      // all warps done reading W before overwriting with partials

    // ---- store partials into Wt region: ps[sl][row][col], row stride 68
    float* ps = Wt;
    #pragma unroll
    for (int rr = 0; rr < 8; rr++) {
        float2 s0 = upk2(acc[rr][0]);
        float2 s1 = upk2(acc[rr][1]);
        ps[sl*PSL_STRIDE + (rbase+rr)*68 + tx]      = s0.x + s0.y;
        ps[sl*PSL_STRIDE + (rbase+rr)*68 + tx + 32] = s1.x + s1.y;
    }
    __syncthreads();

    // ---- reduce 4 slices + epilogue: thread -> 4 consecutive outputs
    {
        int idx0 = tid * 4;              // 0..1020
        int rr = idx0 >> 6, c0 = idx0 & 63;
        const float* base = ps + rr*68 + c0;
        float4 o0 = *(const float4*)(base);
        float4 o1 = *(const float4*)(base + PSL_STRIDE);
        float4 o2 = *(const float4*)(base + 2*PSL_STRIDE);
        float4 o3 = *(const float4*)(base + 3*PSL_STRIDE);
        float v0 = (o0.x + o1.x) + (o2.x + o3.x);
        float v1 = (o0.y + o1.y) + (o2.y + o3.y);
        float v2 = (o0.z + o1.z) + (o2.z + o3.z);
        float v3 = (o0.w + o1.w) + (o2.w + o3.w);

        int gc = ny*64 + c0;
        int row = row0 + rr;
        float4 bb = *(const float4*)&bias[gc];
        v0 += bb.x; v1 += bb.y; v2 += bb.z; v3 += bb.w;
        if (MODE == 1) {
            float4 ad = *(const float4*)&Add[(size_t)row*128 + gc];
            v0 += ad.x; v1 += ad.y; v2 += ad.z; v3 += ad.w;
        }
        if (MODE == 2) {
            float gmv = __ldg(gammaPtr);
            float4 rs = *(const float4*)&Res[(size_t)row*128 + gc];
            v0 = fmaf(gmv, v0, rs.x); v1 = fmaf(gmv, v1, rs.y);
            v2 = fmaf(gmv, v2, rs.z); v3 = fmaf(gmv, v3, rs.w);
        }
        if (MODE == 3) {
            __nv_bfloat16* C = (__nv_bfloat16*)Cv;
            __nv_bfloat162 lo = __floats2bfloat162_rn(v0, v1);
            __nv_bfloat162 hi = __floats2bfloat162_rn(v2, v3);
            uint2 pkd; pkd.x = *(unsigned*)&lo; pkd.y = *(unsigned*)&hi;
            *(uint2*)&C[(size_t)row*128 + gc] = pkd;
        } else {
            float* C = (float*)Cv;
            *(float4*)&C[(size_t)row*128 + gc] = make_float4(v0, v1, v2, v3);
        }
    }
}

// ================= attention v5 (best-known) =================
__global__ void __launch_bounds__(128) attn5(
    const float4* __restrict__ pe4, const int* __restrict__ nposPtr,
    const float* __restrict__ Wp1, const float* __restrict__ bp1,
    const float* __restrict__ scal)
{
    __shared__ float4 sp4[DDIM];
    __shared__ float4 relq[KNBR];
    __shared__ int    ids[KNBR];
    __shared__ float  pl[4*KNBR];
    __shared__ float  red[8];
    __shared__ float  rv[4*DDIM];
    __shared__ float  rh[4*DDIM];

    int p = blockIdx.x, tid = threadIdx.x, lane = tid & 31, wrp = tid >> 5;

    sp4[tid] = __ldg(&pe4[tid]);

    size_t base = (size_t)p * KNBR + tid;
    float4 rq = g_rel4[base];
    int gm = g_idx[base];
    relq[tid] = rq;
    ids[tid] = gm;
    int npos = __ldg(nposPtr);
    __syncthreads();

    {
        float4 r0 = relq[lane];
        float4 r1 = relq[lane + 32];
        float4 r2 = relq[lane + 64];
        float4 r3 = relq[lane + 96];
        float d0 = 0.f, d1 = 0.f, d2 = 0.f, d3 = 0.f;
        int dbase = wrp * 32;
        #pragma unroll 8
        for (int j = 0; j < 32; j++) {
            int d = dbase + j;
            float4 w = sp4[d];
            float h0 = fmaf(r0.x, w.x, fmaf(r0.y, w.y, fmaf(r0.z, w.z, w.w)));
            float h1 = fmaf(r1.x, w.x, fmaf(r1.y, w.y, fmaf(r1.z, w.z, w.w)));
            float h2 = fmaf(r2.x, w.x, fmaf(r2.y, w.y, fmaf(r2.z, w.z, w.w)));
            float h3 = fmaf(r3.x, w.x, fmaf(r3.y, w.y, fmaf(r3.z, w.z, w.w)));
            if (d < npos) {
                d0 += fmaxf(h0, 0.f); d1 += fmaxf(h1, 0.f);
                d2 += fmaxf(h2, 0.f); d3 += fmaxf(h3, 0.f);
            } else {
                d0 += fminf(h0, 0.f); d1 += fminf(h1, 0.f);
                d2 += fminf(h2, 0.f); d3 += fminf(h3, 0.f);
            }
        }
        pl[wrp*KNBR + lane]      = d0;
        pl[wrp*KNBR + lane + 32] = d1;
        pl[wrp*KNBR + lane + 64] = d2;
        pl[wrp*KNBR + lane + 96] = d3;
    }
    __syncthreads();

    float dot = pl[tid] + pl[KNBR+tid] + pl[2*KNBR+tid] + pl[3*KNBR+tid];
    float logit = g_qs[p] - g_ks[gm] + dot + __ldg(&scal[2]);

    float mx = logit;
    #pragma unroll
    for (int o = 16; o; o >>= 1) mx = fmaxf(mx, __shfl_xor_sync(0xffffffffu, mx, o));
    if (!lane) red[wrp] = mx;
    __syncthreads();
    mx = fmaxf(fmaxf(red[0], red[1]), fmaxf(red[2], red[3]));
    float e = expf(logit - mx);
    float ss = e;
    #pragma unroll
    for (int o = 16; o; o >>= 1) ss += __shfl_xor_sync(0xffffffffu, ss, o);
    if (!lane) red[4 + wrp] = ss;
    __syncthreads();
    ss = red[4] + red[5] + red[6] + red[7];
    rq.w = e / ss;
    relq[tid] = rq;
    __syncthreads();

    float4 WX = __ldg((const float4*)&Wp1[lane*4]);
    float4 WY = __ldg((const float4*)&Wp1[DDIM + lane*4]);
    float4 WZ = __ldg((const float4*)&Wp1[2*DDIM + lane*4]);
    float4 BV = __ldg((const float4*)&bp1[lane*4]);

    float av0=0.f, av1=0.f, av2=0.f, av3=0.f;
    float ah0=0.f, ah1=0.f, ah2=0.f, ah3=0.f;
    int kbase = wrp * 32;
    const __nv_bfloat16* vbase = g_vh + lane*4;
    #pragma unroll 8
    for (int j = 0; j < 32; j++) {
        float4 rk = relq[kbase + j];
        int id = ids[kbase + j];
        uint2 raw = __ldg((const uint2*)(vbase + (size_t)id * DDIM));
        float2 f01 = __bfloat1622float2(*(__nv_bfloat162*)&raw.x);
        float2 f23 = __bfloat1622float2(*(__nv_bfloat162*)&raw.y);
        float a = rk.w;
        float h0 = fmaxf(fmaf(rk.x,WX.x,fmaf(rk.y,WY.x,fmaf(rk.z,WZ.x,BV.x))), 0.f);
        float h1 = fmaxf(fmaf(rk.x,WX.y,fmaf(rk.y,WY.y,fmaf(rk.z,WZ.y,BV.y))), 0.f);
        float h2 = fmaxf(fmaf(rk.x,WX.z,fmaf(rk.y,WY.z,fmaf(rk.z,WZ.z,BV.z))), 0.f);
        float h3 = fmaxf(fmaf(rk.x,WX.w,fmaf(rk.y,WY.w,fmaf(rk.z,WZ.w,BV.w))), 0.f);
        ah0 = fmaf(a, h0, ah0); ah1 = fmaf(a, h1, ah1);
        ah2 = fmaf(a, h2, ah2); ah3 = fmaf(a, h3, ah3);
        av0 = fmaf(a, f01.x, av0); av1 = fmaf(a, f01.y, av1);
        av2 = fmaf(a, f23.x, av2); av3 = fmaf(a, f23.y, av3);
    }
    *(float4*)&rv[wrp*DDIM + lane*4] = make_float4(av0, av1, av2, av3);
    *(float4*)&rh[wrp*DDIM + lane*4] = make_float4(ah0, ah1, ah2, ah3);
    __syncthreads();

    float sv = rv[tid] + rv[DDIM+tid] + rv[2*DDIM+tid] + rv[3*DDIM+tid];
    float sh = rh[tid] + rh[DDIM+tid] + rh[2*DDIM+tid] + rh[3*DDIM+tid];
    g_aggv[(size_t)p*DDIM + tid] = sv;
    g_aggh[(size_t)p*DDIM + tid] = sh;
}

// ================= timestep embedding MLP v2 =================
__global__ void __launch_bounds__(512) temb_kernel(
    const int* __restrict__ t,
    const float* __restrict__ tW1, const float* __restrict__ tb1,
    const float* __restrict__ tW2, const float* __restrict__ tb2) {
    __shared__ float emb[128], h1[128], part[4*128];
    int b = blockIdx.x;
    int tid = threadIdx.x;
    int d = tid & 127, iq = tid >> 7;

    if (tid < 128) {
        float tv = (float)__ldg(&t[b]);
        if (tid < 64) {
            float f = expf(-logf(10000.f) * (float)tid / 63.f);
            float arg = tv * f;
            emb[tid] = sinf(arg);
            emb[tid + 64] = cosf(arg);
        }
    }
    __syncthreads();

    {
        float a0 = 0.f, a1 = 0.f, a2 = 0.f, a3 = 0.f;
        int i0 = iq * 32;
        #pragma unroll
        for (int j = 0; j < 32; j += 4) {
            a0 = fmaf(emb[i0+j+0], __ldg(&tW1[(i0+j+0)*128 + d]), a0);
            a1 = fmaf(emb[i0+j+1], __ldg(&tW1[(i0+j+1)*128 + d]), a1);
            a2 = fmaf(emb[i0+j+2], __ldg(&tW1[(i0+j+2)*128 + d]), a2);
            a3 = fmaf(emb[i0+j+3], __ldg(&tW1[(i0+j+3)*128 + d]), a3);
        }
        part[iq*128 + d] = (a0 + a1) + (a2 + a3);
    }
    __syncthreads();
    if (tid < 128)
        h1[tid] = fmaxf(part[tid] + part[128+tid] + part[256+tid] + part[384+tid] + __ldg(&tb1[tid]), 0.f);
    __syncthreads();

    {
        float a0 = 0.f, a1 = 0.f, a2 = 0.f, a3 = 0.f;
        int i0 = iq * 32;
        #pragma unroll
        for (int j = 0; j < 32; j += 4) {
            a0 = fmaf(h1[i0+j+0], __ldg(&tW2[(i0+j+0)*128 + d]), a0);
            a1 = fmaf(h1[i0+j+1], __ldg(&tW2[(i0+j+1)*128 + d]), a1);
            a2 = fmaf(h1[i0+j+2], __ldg(&tW2[(i0+j+2)*128 + d]), a2);
            a3 = fmaf(h1[i0+j+3], __ldg(&tW2[(i0+j+3)*128 + d]), a3);
        }
        part[iq*128 + d] = (a0 + a1) + (a2 + a3);
    }
    __syncthreads();
    if (tid < 128)
        g_temb[b*128 + tid] = part[tid] + part[128+tid] + part[256+tid] + part[384+tid] + __ldg(&tb2[tid]);
}

// ================= final LN+ReLU+proj =================
__global__ void out_kernel(const float* __restrict__ g2, const float* __restrict__ be2,
                           const float* __restrict__ W3, const float* __restrict__ b3,
                           float* __restrict__ out) {
    int p = blockIdx.x * 8 + (threadIdx.x >> 5);
    int lane = threadIdx.x & 31;
    float4 f = ((const float4*)(g_h2 + (size_t)p * DDIM))[lane];
    float s = f.x + f.y + f.z + f.w;
    #pragma unroll
    for (int o = 16; o; o >>= 1) s += __shfl_xor_sync(0xffffffffu, s, o);
    float mean = s * 0.0078125f;
    float d0 = f.x-mean, d1 = f.y-mean, d2 = f.z-mean, d3 = f.w-mean;
    float q = d0*d0 + d1*d1 + d2*d2 + d3*d3;
    #pragma unroll
    for (int o = 16; o; o >>= 1) q += __shfl_xor_sync(0xffffffffu, q, o);
    float rstd = rsqrtf(q * 0.0078125f + 1e-5f);
    int i0 = lane * 4;
    float4 gg = *(const float4*)&g2[i0];
    float4 bb = *(const float4*)&be2[i0];
    float v0 = fmaxf(fmaf(d0*rstd, gg.x, bb.x), 0.f);
    float v1 = fmaxf(fmaf(d1*rstd, gg.y, bb.y), 0.f);
    float v2 = fmaxf(fmaf(d2*rstd, gg.z, bb.z), 0.f);
    float v3 = fmaxf(fmaf(d3*rstd, gg.w, bb.w), 0.f);
    float a0 = v0*W3[i0*3+0] + v1*W3[(i0+1)*3+0] + v2*W3[(i0+2)*3+0] + v3*W3[(i0+3)*3+0];
    float a1 = v0*W3[i0*3+1] + v1*W3[(i0+1)*3+1] + v2*W3[(i0+2)*3+1] + v3*W3[(i0+3)*3+1];
    float a2 = v0*W3[i0*3+2] + v1*W3[(i0+1)*3+2] + v2*W3[(i0+2)*3+2] + v3*W3[(i0+3)*3+2];
    #pragma unroll
    for (int o = 16; o; o >>= 1) {
        a0 += __shfl_xor_sync(0xffffffffu, a0, o);
        a1 += __shfl_xor_sync(0xffffffffu, a1, o);
        a2 += __shfl_xor_sync(0xffffffffu, a2, o);
    }
    if (!lane) {
        out[p*3+0] = a0 + b3[0];
        out[p*3+1] = a1 + b3[1];
        out[p*3+2] = a2 + b3[2];
    }
}

#define KPP128 132
#define SL128  32
#define KPP259 308
#define SL259  76
#define GS(KPp) (80 * (KPp) * 4)

extern "C" void kernel_launch(void* const* d_in, const int* in_sizes, int n_in,
                              void* d_out, int out_size) {
    const float* xyz   = (const float*)d_in[0];
    const float* feat  = (const float*)d_in[1];
    const float* x_t   = (const float*)d_in[2];
    const int*   t     = (const int*)  d_in[3];
    const float* Wq    = (const float*)d_in[4];
    const float* bq    = (const float*)d_in[5];
    const float* Wk    = (const float*)d_in[6];
    const float* bk    = (const float*)d_in[7];
    const float* Wv    = (const float*)d_in[8];
    const float* bv    = (const float*)d_in[9];
    const float* Wp1   = (const float*)d_in[10];
    const float* bp1   = (const float*)d_in[11];
    const float* Wp2   = (const float*)d_in[12];
    const float* bp2   = (const float*)d_in[13];
    const float* gamma = (const float*)d_in[14];
    const float* Wproj = (const float*)d_in[15];
    const float* bproj = (const float*)d_in[16];
    const float* tW1   = (const float*)d_in[17];
    const float* tb1   = (const float*)d_in[18];
    const float* tW2   = (const float*)d_in[19];
    const float* tb2   = (const float*)d_in[20];
    const float* nW1   = (const float*)d_in[21];
    const float* nb1   = (const float*)d_in[22];
    const float* ng1   = (const float*)d_in[23];
    const float* nbe1  = (const float*)d_in[24];
    const float* nW2   = (const float*)d_in[25];
    const float* nb2   = (const float*)d_in[26];
    const float* ng2   = (const float*)d_in[27];
    const float* nbe2  = (const float*)d_in[28];
    const float* nW3   = (const float*)d_in[29];
    const float* nb3   = (const float*)d_in[30];

    cudaFuncSetAttribute(gemm_v6<3,false,false,128,KPP128,SL128>, cudaFuncAttributeMaxDynamicSharedMemorySize, GS(KPP128));
    cudaFuncSetAttribute(gemm_v6<1,false,false,128,KPP128,SL128>, cudaFuncAttributeMaxDynamicSharedMemorySize, GS(KPP128));
    cudaFuncSetAttribute(gemm_v6<2,false,false,128,KPP128,SL128>, cudaFuncAttributeMaxDynamicSharedMemorySize, GS(KPP128));
    cudaFuncSetAttribute(gemm_v6<0,false,true,HCAT,KPP259,SL259>, cudaFuncAttributeMaxDynamicSharedMemorySize, GS(KPP259));
    cudaFuncSetAttribute(gemm_v6<0,true,false,128,KPP128,SL128>,  cudaFuncAttributeMaxDynamicSharedMemorySize, GS(KPP128));

    float *paggv, *paggh, *pt1, *pfA, *pfB, *ph1, *ph2, *pqs, *pks;
    float *pwq, *pwk, *psc, *ptemb;
    float4 *ppe4; int *pnpos;
    __nv_bfloat16 *pvh;
    cudaGetSymbolAddress((void**)&pvh,   g_vh);
    cudaGetSymbolAddress((void**)&paggv, g_aggv);
    cudaGetSymbolAddress((void**)&paggh, g_aggh);
    cudaGetSymbolAddress((void**)&pt1,   g_t1);
    cudaGetSymbolAddress((void**)&pfA,   g_fA);
    cudaGetSymbolAddress((void**)&pfB,   g_fB);
    cudaGetSymbolAddress((void**)&ph1,   g_h1);
    cudaGetSymbolAddress((void**)&ph2,   g_h2);
    cudaGetSymbolAddress((void**)&pqs,   g_qs);
    cudaGetSymbolAddress((void**)&pks,   g_ks);
    cudaGetSymbolAddress((void**)&pwq,   g_wqcs);
    cudaGetSymbolAddress((void**)&pwk,   g_wkcs);
    cudaGetSymbolAddress((void**)&psc,   g_scal);
    cudaGetSymbolAddress((void**)&ppe4,  g_pe4);
    cudaGetSymbolAddress((void**)&pnpos, g_npos);
    cudaGetSymbolAddress((void**)&ptemb, g_temb);

    dim3 ggrid(PP/16, 2);
    const float* cur = feat;
    float* bufs[2] = { pfA, pfB };

    // launch order: knn(0), prep_all(1), prep2(2), vgemm l0(3) <- ncu capture
    knn_kernel<<<PP, 256>>>(xyz);
    prep_all<<<dim3(NLAYER,4), 128>>>(Wq, bq, Wk, bk, Wp2, bp2);
    prep2<<<NLAYER, 128>>>(Wp1, bp1);

    for (int l = 0; l < NLAYER; l++) {
        gemm_v6<3,false,false,128,KPP128,SL128><<<ggrid, 256, GS(KPP128)>>>(cur,
            Wv + (size_t)l*DDIM*DDIM, bv + l*DDIM, pvh,
            nullptr, nullptr, nullptr, nullptr, nullptr,
            pwq + l*DDIM, pwk + l*DDIM, psc + l*4, pqs, pks,
            nullptr, nullptr);
        if (l == 0)
            temb_kernel<<<BB, 512>>>(t, tW1, tb1, tW2, tb2);
        attn5<<<PP, 128>>>(ppe4 + l*DDIM, pnpos + l,
                           Wp1 + (size_t)l*3*DDIM, bp1 + l*DDIM, psc + l*4);
        gemm_v6<1,false,false,128,KPP128,SL128><<<ggrid, 256, GS(KPP128)>>>(paggh,
            Wp2 + (size_t)l*DDIM*DDIM, bp2 + l*DDIM, pt1,
            paggv, nullptr, nullptr, nullptr, nullptr,
            nullptr, nullptr, nullptr, nullptr, nullptr,
            nullptr, nullptr);
        float* nxt = bufs[l & 1];
        gemm_v6<2,false,false,128,KPP128,SL128><<<ggrid, 256, GS(KPP128)>>>(pt1,
            Wproj + (size_t)l*DDIM*DDIM, bproj + l*DDIM, nxt,
            nullptr, cur, gamma + l, nullptr, nullptr,
            nullptr, nullptr, nullptr, nullptr, nullptr,
            nullptr, nullptr);
        cur = nxt;
    }

    gemm_v6<0,false,true,HCAT,KPP259,SL259><<<ggrid, 256, GS(KPP259)>>>(cur,
        nW1, nb1, ph1,
        nullptr, nullptr, nullptr, nullptr, nullptr,
        nullptr, nullptr, nullptr, nullptr, nullptr,
        x_t, ptemb);
    gemm_v6<0,true,false,128,KPP128,SL128><<<ggrid, 256, GS(KPP128)>>>(ph1,
        nW2, nb2, ph2,
        nullptr, nullptr, nullptr, ng1, nbe1,
        nullptr, nullptr, nullptr, nullptr, nullptr,
        nullptr, nullptr);
    out_kernel<<<PP/8, 256>>>(ng2, nbe2, nW3, nb3, (float*)d_out);
}

// round 15
// speedup vs baseline: 1.0759x; 1.0321x over previous
#include <cuda_runtime.h>
#include <cuda_bf16.h>
#include <math.h>

#define BB 2
#define NN 2048
#define DDIM 128
#define KNBR 128
#define NLAYER 4
#define PP (BB*NN)          // 4096 points
#define HCAT 259            // 3 + 128 + 128

typedef unsigned long long ull;

__device__ __forceinline__ ull pk2(float lo, float hi) {
    ull r; asm("mov.b64 %0, {%1, %2};" : "=l"(r) : "f"(lo), "f"(hi)); return r;
}
__device__ __forceinline__ float2 upk2(ull v) {
    float2 r; asm("mov.b64 {%0, %1}, %2;" : "=f"(r.x), "=f"(r.y) : "l"(v)); return r;
}
__device__ __forceinline__ void ffma2(ull& d, ull a, ull b) {
    asm("fma.rn.f32x2 %0, %1, %2, %0;" : "+l"(d) : "l"(a), "l"(b));
}

// ---------------- scratch (device globals) ----------------
__device__ int            g_idx[PP*KNBR];
__device__ float4         g_rel4[PP*KNBR];
__device__ __nv_bfloat16  g_vh[PP*DDIM];
__device__ float          g_qs[PP];
__device__ float          g_ks[PP];
__device__ float          g_agg[PP*2*DDIM];        // [aggh | aggv]
__device__ float          g_fA[PP*DDIM];
__device__ float          g_fB[PP*DDIM];
__device__ float          g_wqcs[NLAYER*DDIM];
__device__ float          g_wkcs[NLAYER*DDIM];
__device__ float          g_scal[NLAYER*4];
__device__ float4         g_pe4[NLAYER*DDIM];      // w2-scaled, sign-sorted
__device__ int            g_npos[NLAYER];
__device__ float          g_temb[BB*DDIM];
__device__ float          g_h1[PP*DDIM];
__device__ float          g_h2[PP*DDIM];
__device__ float          g_wstack[NLAYER*2*DDIM*DDIM];  // [Wf ; Wproj]
__device__ float          g_bf[NLAYER*DDIM];

// ================= KNN =================
__global__ void knn_kernel(const float* __restrict__ xyz) {
    __shared__ float xs[NN*3];
    __shared__ float dsh[NN];
    __shared__ int   red[8];
    __shared__ int   slot;

    int p = blockIdx.x;
    int b = p >> 11;
    int n = p & 2047;
    int tid  = threadIdx.x;
    int lane = tid & 31, wid = tid >> 5;

    const float4* X4 = (const float4*)(xyz + (size_t)b * NN * 3);
    float4* xs4 = (float4*)xs;
    #pragma unroll
    for (int i = tid; i < (NN*3)/4; i += 256) xs4[i] = X4[i];
    __syncthreads();

    float x0 = xs[n*3+0], y0 = xs[n*3+1], z0 = xs[n*3+2];
    float sq0 = x0*x0 + y0*y0 + z0*z0;

    unsigned ul[8];
    #pragma unroll
    for (int i = 0; i < 8; i++) {
        int m = tid + (i << 8);
        float xm = xs[m*3+0], ym = xs[m*3+1], zm = xs[m*3+2];
        float sqm = xm*xm + ym*ym + zm*zm;
        float dot = x0*xm + y0*ym + z0*zm;
        float d = sq0 + sqm - 2.0f*dot;
        dsh[m] = d;
        unsigned u = __float_as_uint(d);
        ul[i] = (u & 0x80000000u) ? ~u : (u | 0x80000000u);
    }
    __syncthreads();

    unsigned lo = 0x80000000u, hi = 0xFFFFFFFFu;
    while (lo < hi) {
        unsigned mid = lo + ((hi - lo) >> 1);
        int c = 0;
        #pragma unroll
        for (int i = 0; i < 8; i++) c += (ul[i] <= mid);
        #pragma unroll
        for (int o = 16; o; o >>= 1) c += __shfl_xor_sync(0xffffffffu, c, o);
        if (!lane) red[wid] = c;
        __syncthreads();
        int tot = red[0]+red[1]+red[2]+red[3]+red[4]+red[5]+red[6]+red[7];
        if (tot >= KNBR) hi = mid; else lo = mid + 1;
        __syncthreads();
    }
    unsigned ustar = lo;

    int c2 = 0;
    #pragma unroll
    for (int i = 0; i < 8; i++) c2 += (ul[i] < ustar);
    #pragma unroll
    for (int o = 16; o; o >>= 1) c2 += __shfl_xor_sync(0xffffffffu, c2, o);
    if (!lane) red[wid] = c2;
    __syncthreads();
    int c_lt = red[0]+red[1]+red[2]+red[3]+red[4]+red[5]+red[6]+red[7];
    int r = KNBR - c_lt;

    if (tid == 0) slot = 0;
    __syncthreads();

    #pragma unroll
    for (int i = 0; i < 8; i++) {
        int m = tid + (i << 8);
        bool sel = false;
        if (ul[i] < ustar) sel = true;
        else if (ul[i] == ustar && r > 0) {
            unsigned mybits = __float_as_uint(dsh[m]);
            int rk = 0;
            for (int mm = 0; mm < m; ++mm)
                rk += (__float_as_uint(dsh[mm]) == mybits);
            if (rk < r) sel = true;
        }
        if (sel) {
            int s = atomicAdd(&slot, 1);
            size_t o = (size_t)p * KNBR + s;
            g_idx[o] = b * NN + m;
            g_rel4[o] = make_float4(x0 - xs[m*3+0], y0 - xs[m*3+1], z0 - xs[m*3+2], 0.f);
        }
    }
}

// ================= prep megakernel: grid (NLAYER, 14), 512 threads ============
// kind 0: Wq row sums  1: Wk row sums  2: bias sums  3: pe4 sort (self w2)
// kind 4: temb (l<BB)  5..12: Wf rows + Wproj copy   13: bf
__global__ void __launch_bounds__(512) prep_mega(
    const float* __restrict__ Wq, const float* __restrict__ bq,
    const float* __restrict__ Wk, const float* __restrict__ bk,
    const float* __restrict__ Wp2, const float* __restrict__ bp2,
    const float* __restrict__ Wp1, const float* __restrict__ bp1,
    const float* __restrict__ Wproj, const float* __restrict__ bproj,
    const int* __restrict__ t,
    const float* __restrict__ tW1, const float* __restrict__ tb1,
    const float* __restrict__ tW2, const float* __restrict__ tb2)
{
    __shared__ float shf[2048];       // union scratch (8KB)
    __shared__ int   cntP[4];

    int l = blockIdx.x, kind = blockIdx.y, tid = threadIdx.x;
    int lane = tid & 31, wid = tid >> 5;

    if (kind < 2) {
        if (tid < 128) {
            const float* W = (kind == 0 ? Wq : Wk) + (size_t)l * DDIM * DDIM;
            float* dst = (kind == 0 ? g_wqcs : g_wkcs) + l * DDIM;
            int seg = tid & 3, rbase = tid >> 2;
            for (int rr = 0; rr < DDIM; rr += 32) {
                int rrow = rbase + rr;
                const float4* row = (const float4*)(W + (size_t)rrow * DDIM + seg * 32);
                float s = 0.f;
                #pragma unroll
                for (int j = 0; j < 8; j++) { float4 v = row[j]; s += v.x + v.y + v.z + v.w; }
                s += __shfl_xor_sync(0xffffffffu, s, 1);
                s += __shfl_xor_sync(0xffffffffu, s, 2);
                if (seg == 0) dst[rrow] = s;
            }
        }
    } else if (kind == 2) {
        if (wid < 3) {
            const float* bb = (wid == 0 ? bq : wid == 1 ? bk : bp2) + l * DDIM;
            float s = bb[lane] + bb[lane+32] + bb[lane+64] + bb[lane+96];
            #pragma unroll
            for (int o = 16; o; o >>= 1) s += __shfl_xor_sync(0xffffffffu, s, o);
            if (!lane) g_scal[l*4 + wid] = s;
        }
    } else if (kind == 3) {
        // self-compute w2 col sums (4 threads per row), then sign-sort pe4
        {
            int rr = tid >> 2, q = tid & 3;
            const float4* row = (const float4*)(Wp2 + (size_t)l*DDIM*DDIM + (size_t)rr*DDIM + q*32);
            float s = 0.f;
            #pragma unroll
            for (int j = 0; j < 8; j++) { float4 v = row[j]; s += v.x + v.y + v.z + v.w; }
            s += __shfl_xor_sync(0xffffffffu, s, 1);
            s += __shfl_xor_sync(0xffffffffu, s, 2);
            if (q == 0) shf[rr] = s;
        }
        __syncthreads();
        float w2 = 0.f; bool pos = false;
        if (tid < 128) { w2 = shf[tid]; pos = w2 > 0.f; }
        if (wid < 4) {
            unsigned bal = __ballot_sync(0xffffffffu, pos);
            if (!lane) cntP[wid] = __popc(bal);
            shf[256 + tid] = (float)__popc(bal & ((1u << lane) - 1u));   // wp
        }
        __syncthreads();
        if (tid < 128) {
            int wp = (int)shf[256 + tid];
            int offP = 0, npos = 0;
            #pragma unroll
            for (int w = 0; w < 4; w++) {
                if (w < wid) offP += cntP[w];
                npos += cntP[w];
            }
            int offN = wid * 32 - offP;
            int wn = lane - wp;
            int dest = pos ? (offP + wp) : (npos + offN + wn);
            const float* W = Wp1 + (size_t)l * 3 * DDIM;
            g_pe4[l*DDIM + dest] = make_float4(W[tid]*w2, W[DDIM+tid]*w2,
                                               W[2*DDIM+tid]*w2, bp1[l*DDIM+tid]*w2);
            if (tid == 0) g_npos[l] = npos;
        }
    } else if (kind == 4) {
        if (l >= BB) return;
        float* emb  = shf;          // 128
        float* h1   = shf + 128;    // 128
        float* part = shf + 256;    // 512
        int b = l, d = tid & 127, iq = tid >> 7;
        if (tid < 64) {
            float tv = (float)__ldg(&t[b]);
            float f = expf(-logf(10000.f) * (float)tid / 63.f);
            float arg = tv * f;
            emb[tid] = sinf(arg);
            emb[tid + 64] = cosf(arg);
        }
        __syncthreads();
        {
            float a0=0.f,a1=0.f,a2=0.f,a3=0.f;
            int i0 = iq * 32;
            #pragma unroll
            for (int j = 0; j < 32; j += 4) {
                a0 = fmaf(emb[i0+j+0], __ldg(&tW1[(i0+j+0)*128 + d]), a0);
                a1 = fmaf(emb[i0+j+1], __ldg(&tW1[(i0+j+1)*128 + d]), a1);
                a2 = fmaf(emb[i0+j+2], __ldg(&tW1[(i0+j+2)*128 + d]), a2);
                a3 = fmaf(emb[i0+j+3], __ldg(&tW1[(i0+j+3)*128 + d]), a3);
            }
            part[iq*128 + d] = (a0 + a1) + (a2 + a3);
        }
        __syncthreads();
        if (tid < 128)
            h1[tid] = fmaxf(part[tid] + part[128+tid] + part[256+tid] + part[384+tid] + __ldg(&tb1[tid]), 0.f);
        __syncthreads();
        {
            float a0=0.f,a1=0.f,a2=0.f,a3=0.f;
            int i0 = iq * 32;
            #pragma unroll
            for (int j = 0; j < 32; j += 4) {
                a0 = fmaf(h1[i0+j+0], __ldg(&tW2[(i0+j+0)*128 + d]), a0);
                a1 = fmaf(h1[i0+j+1], __ldg(&tW2[(i0+j+1)*128 + d]), a1);
                a2 = fmaf(h1[i0+j+2], __ldg(&tW2[(i0+j+2)*128 + d]), a2);
                a3 = fmaf(h1[i0+j+3], __ldg(&tW2[(i0+j+3)*128 + d]), a3);
            }
            part[iq*128 + d] = (a0 + a1) + (a2 + a3);
        }
        __syncthreads();
        if (tid < 128)
            g_temb[b*128 + tid] = part[tid] + part[128+tid] + part[256+tid] + part[384+tid] + __ldg(&tb2[tid]);
    } else if (kind < 13) {
        // Wf rows r0..r0+16 = Wp2[r,:] @ Wproj ; plus copy Wproj rows r0..+16
        int r0 = (kind - 5) * 16;
        const float* Wp2l = Wp2 + (size_t)l*DDIM*DDIM;
        const float* Wprl = Wproj + (size_t)l*DDIM*DDIM;
        float* ws = g_wstack + (size_t)l*2*DDIM*DDIM;
        // stage Wp2 tile [16][128]
        for (int i = tid; i < 16*128; i += 512)
            shf[i] = Wp2l[(size_t)(r0 + (i >> 7))*DDIM + (i & 127)];
        __syncthreads();
        int c = tid & 127, rg = tid >> 7;      // rg 0..3 -> rows rg*4..+4
        float a0=0.f,a1=0.f,a2=0.f,a3=0.f;
        #pragma unroll 4
        for (int k = 0; k < DDIM; k++) {
            float wpr = __ldg(&Wprl[(size_t)k*DDIM + c]);
            a0 = fmaf(shf[(rg*4+0)*128 + k], wpr, a0);
            a1 = fmaf(shf[(rg*4+1)*128 + k], wpr, a1);
            a2 = fmaf(shf[(rg*4+2)*128 + k], wpr, a2);
            a3 = fmaf(shf[(rg*4+3)*128 + k], wpr, a3);
        }
        ws[(size_t)(r0 + rg*4 + 0)*DDIM + c] = a0;
        ws[(size_t)(r0 + rg*4 + 1)*DDIM + c] = a1;
        ws[(size_t)(r0 + rg*4 + 2)*DDIM + c] = a2;
        ws[(size_t)(r0 + rg*4 + 3)*DDIM + c] = a3;
        for (int i = tid; i < 16*128; i += 512)
            ws[(size_t)(128 + r0 + (i >> 7))*DDIM + (i & 127)] =
                Wprl[(size_t)(r0 + (i >> 7))*DDIM + (i & 127)];
    } else {
        // bf = bp2 @ Wproj + bproj
        if (tid < 128) {
            const float* Wp = Wproj + (size_t)l*DDIM*DDIM;
            const float* b2 = bp2 + l*DDIM;
            float a0=0.f,a1=0.f,a2=0.f,a3=0.f;
            #pragma unroll 8
            for (int j = 0; j < DDIM; j += 4) {
                a0 = fmaf(__ldg(&b2[j+0]), __ldg(&Wp[(j+0)*DDIM + tid]), a0);
                a1 = fmaf(__ldg(&b2[j+1]), __ldg(&Wp[(j+1)*DDIM + tid]), a1);
                a2 = fmaf(__ldg(&b2[j+2]), __ldg(&Wp[(j+2)*DDIM + tid]), a2);
                a3 = fmaf(__ldg(&b2[j+3]), __ldg(&Wp[(j+3)*DDIM + tid]), a3);
            }
            g_bf[l*DDIM + tid] = (a0+a1) + (a2+a3) + __ldg(&bproj[l*DDIM + tid]);
        }
    }
}

// ================= GEMM v7: split-K, 256 threads, optional bf16 W tile ========
// MODE: 0 = +bias fp32; 2 = Res+gamma*(acc+bias); 3 = +bias bf16 + qs/ks
// LNA: LN+ReLU on A rows (K=128); CAT: A from [x_t | fused | temb]
#define PSL_STRIDE 1088      // per-slice floats: 16 rows * 68
template<int MODE, bool LNA, bool CAT, int KK, int KPA, int KPW, int SLICE, bool WB16>
__global__ void __launch_bounds__(256, 4) gemm_v7(
    const float* __restrict__ A,
    const float* __restrict__ W,
    const float* __restrict__ bias,
    void* __restrict__ Cv,
    const float* __restrict__ Res,
    const float* __restrict__ gammaPtr,
    const float* __restrict__ lng, const float* __restrict__ lnb,
    const float* __restrict__ wq, const float* __restrict__ wk,
    const float* __restrict__ scal2,
    float* __restrict__ qs, float* __restrict__ ks,
    const float* __restrict__ xt, const float* __restrict__ te)
{
    extern __shared__ float sm[];
    float* As = sm;                                   // 16 * KPA floats
    float* Wtf = sm + 16 * KPA;                       // fp32 W: 64 * KPW floats
    __nv_bfloat16* Wtb = (__nv_bfloat16*)(sm + 16*KPA);  // bf16 W: 64 * KPW bf16

    int tid = threadIdx.x, tx = tid & 31, wrp = tid >> 5;
    int row0 = blockIdx.x * 16, ny = blockIdx.y;

    // ---- A tile
    if (CAT) {
        #pragma unroll 2
        for (int i = tid; i < 16*KPA; i += 256) {
            int rr = i / KPA, c = i - rr*KPA;
            int row = row0 + rr;
            float v = 0.f;
            if (c < 3)        v = xt[row*3 + c];
            else if (c < 131) v = A[(size_t)row*DDIM + (c-3)];
            else if (c < 259) v = te[(row >> 11)*DDIM + (c-131)];
            As[i] = v;
        }
    } else {
        constexpr int K4 = KK >> 2, KP4 = KPA >> 2;
        const float4* A4 = (const float4*)A;
        float4* As4 = (float4*)As;
        #pragma unroll 2
        for (int i = tid; i < 16*KP4; i += 256) {
            int rr = i / KP4, c = i - rr*KP4;
            As4[i] = (c < K4) ? A4[(size_t)(row0+rr)*K4 + c] : make_float4(0.f,0.f,0.f,0.f);
        }
    }

    // ---- W half, transposed into [c][k]
    {
        #pragma unroll 2
        for (int i = tid; i < 16*KPW; i += 256) {
            int c = i & 63, kb4 = i >> 6;
            int k0 = kb4 << 2;
            float w0 = (k0+0 < KK) ? W[(size_t)(k0+0)*128 + ny*64 + c] : 0.f;
            float w1 = (k0+1 < KK) ? W[(size_t)(k0+1)*128 + ny*64 + c] : 0.f;
            float w2 = (k0+2 < KK) ? W[(size_t)(k0+2)*128 + ny*64 + c] : 0.f;
            float w3 = (k0+3 < KK) ? W[(size_t)(k0+3)*128 + ny*64 + c] : 0.f;
            if (WB16) {
                __nv_bfloat162 blo = __floats2bfloat162_rn(w0, w1);
                __nv_bfloat162 bhi = __floats2bfloat162_rn(w2, w3);
                uint2 pkd; pkd.x = *(unsigned*)&blo; pkd.y = *(unsigned*)&bhi;
                *(uint2*)&Wtb[c*KPW + k0] = pkd;
            } else {
                *(float4*)&Wtf[c*KPW + k0] = make_float4(w0, w1, w2, w3);
            }
        }
    }
    __syncthreads();

    // ---- optional LN+ReLU on A rows (K==128)
    if (LNA) {
        int rrow = tid >> 4, seg = tid & 15;
        float* rowp = As + rrow*KPA + seg*8;
        float s = 0.f;
        #pragma unroll
        for (int j = 0; j < 8; j++) s += rowp[j];
        s += __shfl_xor_sync(0xffffffffu, s, 1);
        s += __shfl_xor_sync(0xffffffffu, s, 2);
        s += __shfl_xor_sync(0xffffffffu, s, 4);
        s += __shfl_xor_sync(0xffffffffu, s, 8);
        float mean = s * 0.0078125f;
        float q = 0.f;
        #pragma unroll
        for (int j = 0; j < 8; j++) { float d = rowp[j] - mean; q = fmaf(d, d, q); }
        q += __shfl_xor_sync(0xffffffffu, q, 1);
        q += __shfl_xor_sync(0xffffffffu, q, 2);
        q += __shfl_xor_sync(0xffffffffu, q, 4);
        q += __shfl_xor_sync(0xffffffffu, q, 8);
        float rstd = rsqrtf(q * 0.0078125f + 1e-5f);
        #pragma unroll
        for (int j = 0; j < 8; j++) {
            int c = seg*8 + j;
            rowp[j] = fmaxf(fmaf((rowp[j]-mean)*rstd, __ldg(&lng[c]), __ldg(&lnb[c])), 0.f);
        }
        __syncthreads();
    }

    // ---- fused qs/ks (v-gemm, half 0)
    if (MODE == 3 && ny == 0) {
        int rrow = tid >> 4, seg = tid & 15;
        const float* rowp = As + rrow*KPA + seg*8;
        float dq = 0.f, dk = 0.f;
        #pragma unroll
        for (int j = 0; j < 8; j++) {
            float a = rowp[j];
            dq = fmaf(a, __ldg(&wq[seg*8+j]), dq);
            dk = fmaf(a, __ldg(&wk[seg*8+j]), dk);
        }
        dq += __shfl_xor_sync(0xffffffffu, dq, 1);
        dq += __shfl_xor_sync(0xffffffffu, dq, 2);
        dq += __shfl_xor_sync(0xffffffffu, dq, 4);
        dq += __shfl_xor_sync(0xffffffffu, dq, 8);
        dk += __shfl_xor_sync(0xffffffffu, dk, 1);
        dk += __shfl_xor_sync(0xffffffffu, dk, 2);
        dk += __shfl_xor_sync(0xffffffffu, dk, 4);
        dk += __shfl_xor_sync(0xffffffffu, dk, 8);
        if (seg == 0) {
            qs[row0 + rrow] = dq + __ldg(&scal2[0]);
            ks[row0 + rrow] = dk + __ldg(&scal2[1]);
        }
    }

    // ---- main loop: slice sl = wrp>>1, rows rbase = (wrp&1)*8
    int sl = wrp >> 1, rbase = (wrp & 1) * 8;
    ull acc[8][2];
    #pragma unroll
    for (int rr = 0; rr < 8; rr++) { acc[rr][0] = pk2(0.f,0.f); acc[rr][1] = pk2(0.f,0.f); }

    {
        const float* ab = As + rbase*KPA;
        int kend = sl*SLICE + SLICE;
        if (WB16) {
            const __nv_bfloat16* w0p = Wtb + tx*KPW;
            const __nv_bfloat16* w1p = Wtb + (tx+32)*KPW;
            #pragma unroll 4
            for (int kb = sl*SLICE; kb < kend; kb += 4) {
                uint2 wra = *(const uint2*)&w0p[kb];
                uint2 wrb = *(const uint2*)&w1p[kb];
                float2 la = __bfloat1622float2(*(__nv_bfloat162*)&wra.x);
                float2 ha = __bfloat1622float2(*(__nv_bfloat162*)&wra.y);
                float2 lb = __bfloat1622float2(*(__nv_bfloat162*)&wrb.x);
                float2 hb = __bfloat1622float2(*(__nv_bfloat162*)&wrb.y);
                ull waL = pk2(la.x, la.y), waH = pk2(ha.x, ha.y);
                ull wbL = pk2(lb.x, lb.y), wbH = pk2(hb.x, hb.y);
                #pragma unroll
                for (int rr = 0; rr < 8; rr++) {
                    float4 av = *(const float4*)&ab[rr*KPA + kb];
                    ull aL = pk2(av.x, av.y), aH = pk2(av.z, av.w);
                    ffma2(acc[rr][0], aL, waL); ffma2(acc[rr][0], aH, waH);
                    ffma2(acc[rr][1], aL, wbL); ffma2(acc[rr][1], aH, wbH);
                }
            }
        } else {
            const float* w0p = Wtf + tx*KPW;
            const float* w1p = Wtf + (tx+32)*KPW;
            #pragma unroll 4
            for (int kb = sl*SLICE; kb < kend; kb += 4) {
                float4 wa = *(const float4*)&w0p[kb];
                float4 wb = *(const float4*)&w1p[kb];
                ull waL = pk2(wa.x, wa.y), waH = pk2(wa.z, wa.w);
                ull wbL = pk2(wb.x, wb.y), wbH = pk2(wb.z, wb.w);
                #pragma unroll
                for (int rr = 0; rr < 8; rr++) {
                    float4 av = *(const float4*)&ab[rr*KPA + kb];
                    ull aL = pk2(av.x, av.y), aH = pk2(av.z, av.w);
                    ffma2(acc[rr][0], aL, waL); ffma2(acc[rr][0], aH, waH);
                    ffma2(acc[rr][1], aL, wbL); ffma2(acc[rr][1], aH, wbH);
                }
            }
        }
    }
    __syncthreads();

    // ---- partials into W region
    float* ps = (float*)(sm + 16*KPA);
    #pragma unroll
    for (int rr = 0; rr < 8; rr++) {
        float2 s0 = upk2(acc[rr][0]);
        float2 s1 = upk2(acc[rr][1]);
        ps[sl*PSL_STRIDE + (rbase+rr)*68 + tx]      = s0.x + s0.y;
        ps[sl*PSL_STRIDE + (rbase+rr)*68 + tx + 32] = s1.x + s1.y;
    }
    __syncthreads();

    // ---- reduce 4 slices + epilogue
    {
        int idx0 = tid * 4;
        int rr = idx0 >> 6, c0 = idx0 & 63;
        const float* base = ps + rr*68 + c0;
        float4 o0 = *(const float4*)(base);
        float4 o1 = *(const float4*)(base + PSL_STRIDE);
        float4 o2 = *(const float4*)(base + 2*PSL_STRIDE);
        float4 o3 = *(const float4*)(base + 3*PSL_STRIDE);
        float v0 = (o0.x + o1.x) + (o2.x + o3.x);
        float v1 = (o0.y + o1.y) + (o2.y + o3.y);
        float v2 = (o0.z + o1.z) + (o2.z + o3.z);
        float v3 = (o0.w + o1.w) + (o2.w + o3.w);

        int gc = ny*64 + c0;
        int row = row0 + rr;
        float4 bb = *(const float4*)&bias[gc];
        v0 += bb.x; v1 += bb.y; v2 += bb.z; v3 += bb.w;
        if (MODE == 2) {
            float gmv = __ldg(gammaPtr);
            float4 rs = *(const float4*)&Res[(size_t)row*128 + gc];
            v0 = fmaf(gmv, v0, rs.x); v1 = fmaf(gmv, v1, rs.y);
            v2 = fmaf(gmv, v2, rs.z); v3 = fmaf(gmv, v3, rs.w);
        }
        if (MODE == 3) {
            __nv_bfloat16* C = (__nv_bfloat16*)Cv;
            __nv_bfloat162 blo = __floats2bfloat162_rn(v0, v1);
            __nv_bfloat162 bhi = __floats2bfloat162_rn(v2, v3);
            uint2 pkd; pkd.x = *(unsigned*)&blo; pkd.y = *(unsigned*)&bhi;
            *(uint2*)&C[(size_t)row*128 + gc] = pkd;
        } else {
            float* C = (float*)Cv;
            *(float4*)&C[(size_t)row*128 + gc] = make_float4(v0, v1, v2, v3);
        }
    }
}

// ================= attention v5 (writes [aggh|aggv]) =================
__global__ void __launch_bounds__(128) attn5(
    const float4* __restrict__ pe4, const int* __restrict__ nposPtr,
    const float* __restrict__ Wp1, const float* __restrict__ bp1,
    const float* __restrict__ scal)
{
    __shared__ float4 sp4[DDIM];
    __shared__ float4 relq[KNBR];
    __shared__ int    ids[KNBR];
    __shared__ float  pl[4*KNBR];
    __shared__ float  red[8];
    __shared__ float  rv[4*DDIM];
    __shared__ float  rh[4*DDIM];

    int p = blockIdx.x, tid = threadIdx.x, lane = tid & 31, wrp = tid >> 5;

    sp4[tid] = __ldg(&pe4[tid]);

    size_t base = (size_t)p * KNBR + tid;
    float4 rq = g_rel4[base];
    int gm = g_idx[base];
    relq[tid] = rq;
    ids[tid] = gm;
    int npos = __ldg(nposPtr);
    __syncthreads();

    {
        float4 r0 = relq[lane];
        float4 r1 = relq[lane + 32];
        float4 r2 = relq[lane + 64];
        float4 r3 = relq[lane + 96];
        float d0 = 0.f, d1 = 0.f, d2 = 0.f, d3 = 0.f;
        int dbase = wrp * 32;
        #pragma unroll 8
        for (int j = 0; j < 32; j++) {
            int d = dbase + j;
            float4 w = sp4[d];
            float h0 = fmaf(r0.x, w.x, fmaf(r0.y, w.y, fmaf(r0.z, w.z, w.w)));
            float h1 = fmaf(r1.x, w.x, fmaf(r1.y, w.y, fmaf(r1.z, w.z, w.w)));
            float h2 = fmaf(r2.x, w.x, fmaf(r2.y, w.y, fmaf(r2.z, w.z, w.w)));
            float h3 = fmaf(r3.x, w.x, fmaf(r3.y, w.y, fmaf(r3.z, w.z, w.w)));
            if (d < npos) {
                d0 += fmaxf(h0, 0.f); d1 += fmaxf(h1, 0.f);
                d2 += fmaxf(h2, 0.f); d3 += fmaxf(h3, 0.f);
            } else {
                d0 += fminf(h0, 0.f); d1 += fminf(h1, 0.f);
                d2 += fminf(h2, 0.f); d3 += fminf(h3, 0.f);
            }
        }
        pl[wrp*KNBR + lane]      = d0;
        pl[wrp*KNBR + lane + 32] = d1;
        pl[wrp*KNBR + lane + 64] = d2;
        pl[wrp*KNBR + lane + 96] = d3;
    }
    __syncthreads();

    float dot = pl[tid] + pl[KNBR+tid] + pl[2*KNBR+tid] + pl[3*KNBR+tid];
    float logit = g_qs[p] - g_ks[gm] + dot + __ldg(&scal[2]);

    float mx = logit;
    #pragma unroll
    for (int o = 16; o; o >>= 1) mx = fmaxf(mx, __shfl_xor_sync(0xffffffffu, mx, o));
    if (!lane) red[wrp] = mx;
    __syncthreads();
    mx = fmaxf(fmaxf(red[0], red[1]), fmaxf(red[2], red[3]));
    float e = expf(logit - mx);
    float ss = e;
    #pragma unroll
    for (int o = 16; o; o >>= 1) ss += __shfl_xor_sync(0xffffffffu, ss, o);
    if (!lane) red[4 + wrp] = ss;
    __syncthreads();
    ss = red[4] + red[5] + red[6] + red[7];
    rq.w = e / ss;
    relq[tid] = rq;
    __syncthreads();

    float4 WX = __ldg((const float4*)&Wp1[lane*4]);
    float4 WY = __ldg((const float4*)&Wp1[DDIM + lane*4]);
    float4 WZ = __ldg((const float4*)&Wp1[2*DDIM + lane*4]);
    float4 BV = __ldg((const float4*)&bp1[lane*4]);

    float av0=0.f, av1=0.f, av2=0.f, av3=0.f;
    float ah0=0.f, ah1=0.f, ah2=0.f, ah3=0.f;
    int kbase = wrp * 32;
    const __nv_bfloat16* vbase = g_vh + lane*4;
    #pragma unroll 8
    for (int j = 0; j < 32; j++) {
        float4 rk = relq[kbase + j];
        int id = ids[kbase + j];
        uint2 raw = __ldg((const uint2*)(vbase + (size_t)id * DDIM));
        float2 f01 = __bfloat1622float2(*(__nv_bfloat162*)&raw.x);
        float2 f23 = __bfloat1622float2(*(__nv_bfloat162*)&raw.y);
        float a = rk.w;
        float h0 = fmaxf(fmaf(rk.x,WX.x,fmaf(rk.y,WY.x,fmaf(rk.z,WZ.x,BV.x))), 0.f);
        float h1 = fmaxf(fmaf(rk.x,WX.y,fmaf(rk.y,WY.y,fmaf(rk.z,WZ.y,BV.y))), 0.f);
        float h2 = fmaxf(fmaf(rk.x,WX.z,fmaf(rk.y,WY.z,fmaf(rk.z,WZ.z,BV.z))), 0.f);
        float h3 = fmaxf(fmaf(rk.x,WX.w,fmaf(rk.y,WY.w,fmaf(rk.z,WZ.w,BV.w))), 0.f);
        ah0 = fmaf(a, h0, ah0); ah1 = fmaf(a, h1, ah1);
        ah2 = fmaf(a, h2, ah2); ah3 = fmaf(a, h3, ah3);
        av0 = fmaf(a, f01.x, av0); av1 = fmaf(a, f01.y, av1);
        av2 = fmaf(a, f23.x, av2); av3 = fmaf(a, f23.y, av3);
    }
    *(float4*)&rv[wrp*DDIM + lane*4] = make_float4(av0, av1, av2, av3);
    *(float4*)&rh[wrp*DDIM + lane*4] = make_float4(ah0, ah1, ah2, ah3);
    __syncthreads();

    float sv = rv[tid] + rv[DDIM+tid] + rv[2*DDIM+tid] + rv[3*DDIM+tid];
    float sh = rh[tid] + rh[DDIM+tid] + rh[2*DDIM+tid] + rh[3*DDIM+tid];
    g_agg[(size_t)p*2*DDIM + tid]        = sh;     // aggh
    g_agg[(size_t)p*2*DDIM + DDIM + tid] = sv;     // aggv
}

// ================= final LN+ReLU+proj =================
__global__ void out_kernel(const float* __restrict__ g2, const float* __restrict__ be2,
                           const float* __restrict__ W3, const float* __restrict__ b3,
                           float* __restrict__ out) {
    int p = blockIdx.x * 8 + (threadIdx.x >> 5);
    int lane = threadIdx.x & 31;
    float4 f = ((const float4*)(g_h2 + (size_t)p * DDIM))[lane];
    float s = f.x + f.y + f.z + f.w;
    #pragma unroll
    for (int o = 16; o; o >>= 1) s += __shfl_xor_sync(0xffffffffu, s, o);
    float mean = s * 0.0078125f;
    float d0 = f.x-mean, d1 = f.y-mean, d2 = f.z-mean, d3 = f.w-mean;
    float q = d0*d0 + d1*d1 + d2*d2 + d3*d3;
    #pragma unroll
    for (int o = 16; o; o >>= 1) q += __shfl_xor_sync(0xffffffffu, q, o);
    float rstd = rsqrtf(q * 0.0078125f + 1e-5f);
    int i0 = lane * 4;
    float4 gg = *(const float4*)&g2[i0];
    float4 bb = *(const float4*)&be2[i0];
    float v0 = fmaxf(fmaf(d0*rstd, gg.x, bb.x), 0.f);
    float v1 = fmaxf(fmaf(d1*rstd, gg.y, bb.y), 0.f);
    float v2 = fmaxf(fmaf(d2*rstd, gg.z, bb.z), 0.f);
    float v3 = fmaxf(fmaf(d3*rstd, gg.w, bb.w), 0.f);
    float a0 = v0*W3[i0*3+0] + v1*W3[(i0+1)*3+0] + v2*W3[(i0+2)*3+0] + v3*W3[(i0+3)*3+0];
    float a1 = v0*W3[i0*3+1] + v1*W3[(i0+1)*3+1] + v2*W3[(i0+2)*3+1] + v3*W3[(i0+3)*3+1];
    float a2 = v0*W3[i0*3+2] + v1*W3[(i0+1)*3+2] + v2*W3[(i0+2)*3+2] + v3*W3[(i0+3)*3+2];
    #pragma unroll
    for (int o = 16; o; o >>= 1) {
        a0 += __shfl_xor_sync(0xffffffffu, a0, o);
        a1 += __shfl_xor_sync(0xffffffffu, a1, o);
        a2 += __shfl_xor_sync(0xffffffffu, a2, o);
    }
    if (!lane) {
        out[p*3+0] = a0 + b3[0];
        out[p*3+1] = a1 + b3[1];
        out[p*3+2] = a2 + b3[2];
    }
}

// smem sizes
#define GS128  ((16*132 + 64*132) * 4)                 // 42240
#define GSMRG  (16*260*4 + 64*276*2)                   // 51968
#define GS259  ((16*308 + 64*308) * 4)                 // 98560

extern "C" void kernel_launch(void* const* d_in, const int* in_sizes, int n_in,
                              void* d_out, int out_size) {
    const float* xyz   = (const float*)d_in[0];
    const float* feat  = (const float*)d_in[1];
    const float* x_t   = (const float*)d_in[2];
    const int*   t     = (const int*)  d_in[3];
    const float* Wq    = (const float*)d_in[4];
    const float* bq    = (const float*)d_in[5];
    const float* Wk    = (const float*)d_in[6];
    const float* bk    = (const float*)d_in[7];
    const float* Wv    = (const float*)d_in[8];
    const float* bv    = (const float*)d_in[9];
    const float* Wp1   = (const float*)d_in[10];
    const float* bp1   = (const float*)d_in[11];
    const float* Wp2   = (const float*)d_in[12];
    const float* bp2   = (const float*)d_in[13];
    const float* gamma = (const float*)d_in[14];
    const float* Wproj = (const float*)d_in[15];
    const float* bproj = (const float*)d_in[16];
    const float* tW1   = (const float*)d_in[17];
    const float* tb1   = (const float*)d_in[18];
    const float* tW2   = (const float*)d_in[19];
    const float* tb2   = (const float*)d_in[20];
    const float* nW1   = (const float*)d_in[21];
    const float* nb1   = (const float*)d_in[22];
    const float* ng1   = (const float*)d_in[23];
    const float* nbe1  = (const float*)d_in[24];
    const float* nW2   = (const float*)d_in[25];
    const float* nb2   = (const float*)d_in[26];
    const float* ng2   = (const float*)d_in[27];
    const float* nbe2  = (const float*)d_in[28];
    const float* nW3   = (const float*)d_in[29];
    const float* nb3   = (const float*)d_in[30];

    cudaFuncSetAttribute(gemm_v7<3,false,false,128,132,132,32,false>, cudaFuncAttributeMaxDynamicSharedMemorySize, GS128);
    cudaFuncSetAttribute(gemm_v7<2,false,false,256,260,276,68,true>,  cudaFuncAttributeMaxDynamicSharedMemorySize, GSMRG);
    cudaFuncSetAttribute(gemm_v7<0,false,true,HCAT,308,308,76,false>, cudaFuncAttributeMaxDynamicSharedMemorySize, GS259);
    cudaFuncSetAttribute(gemm_v7<0,true,false,128,132,132,32,false>,  cudaFuncAttributeMaxDynamicSharedMemorySize, GS128);

    float *pagg, *pfA, *pfB, *ph1, *ph2, *pqs, *pks;
    float *pwq, *pwk, *psc, *ptemb, *pwstack, *pbf;
    float4 *ppe4; int *pnpos;
    __nv_bfloat16 *pvh;
    cudaGetSymbolAddress((void**)&pvh,    g_vh);
    cudaGetSymbolAddress((void**)&pagg,   g_agg);
    cudaGetSymbolAddress((void**)&pfA,    g_fA);
    cudaGetSymbolAddress((void**)&pfB,    g_fB);
    cudaGetSymbolAddress((void**)&ph1,    g_h1);
    cudaGetSymbolAddress((void**)&ph2,    g_h2);
    cudaGetSymbolAddress((void**)&pqs,    g_qs);
    cudaGetSymbolAddress((void**)&pks,    g_ks);
    cudaGetSymbolAddress((void**)&pwq,    g_wqcs);
    cudaGetSymbolAddress((void**)&pwk,    g_wkcs);
    cudaGetSymbolAddress((void**)&psc,    g_scal);
    cudaGetSymbolAddress((void**)&ppe4,   g_pe4);
    cudaGetSymbolAddress((void**)&pnpos,  g_npos);
    cudaGetSymbolAddress((void**)&ptemb,  g_temb);
    cudaGetSymbolAddress((void**)&pwstack,g_wstack);
    cudaGetSymbolAddress((void**)&pbf,    g_bf);

    dim3 ggrid(PP/16, 2);
    const float* cur = feat;
    float* bufs[2] = { pfA, pfB };

    knn_kernel<<<PP, 256>>>(xyz);
    prep_mega<<<dim3(NLAYER,14), 512>>>(Wq, bq, Wk, bk, Wp2, bp2, Wp1, bp1,
                                        Wproj, bproj, t, tW1, tb1, tW2, tb2);

    for (int l = 0; l < NLAYER; l++) {
        gemm_v7<3,false,false,128,132,132,32,false><<<ggrid, 256, GS128>>>(cur,
            Wv + (size_t)l*DDIM*DDIM, bv + l*DDIM, pvh,
            nullptr, nullptr, nullptr, nullptr,
            pwq + l*DDIM, pwk + l*DDIM, psc + l*4, pqs, pks,
            nullptr, nullptr);
        attn5<<<PP, 128>>>(ppe4 + l*DDIM, pnpos + l,
                           Wp1 + (size_t)l*3*DDIM, bp1 + l*DDIM, psc + l*4);
        float* nxt = bufs[l & 1];
        gemm_v7<2,false,false,256,260,276,68,true><<<ggrid, 256, GSMRG>>>(pagg,
            pwstack + (size_t)l*2*DDIM*DDIM, pbf + l*DDIM, nxt,
            cur, gamma + l, nullptr, nullptr,
            nullptr, nullptr, nullptr, nullptr, nullptr,
            nullptr, nullptr);
        cur = nxt;
    }

    gemm_v7<0,false,true,HCAT,308,308,76,false><<<ggrid, 256, GS259>>>(cur,
        nW1, nb1, ph1,
        nullptr, nullptr, nullptr, nullptr,
        nullptr, nullptr, nullptr, nullptr, nullptr,
        x_t, ptemb);
    gemm_v7<0,true,false,128,132,132,32,false><<<ggrid, 256, GS128>>>(ph1,
        nW2, nb2, ph2,
        nullptr, nullptr, ng1, nbe1,
        nullptr, nullptr, nullptr, nullptr, nullptr,
        nullptr, nullptr);
    out_kernel<<<PP/8, 256>>>(ng2, nbe2, nW3, nb3, (float*)d_out);
}